// round 1
// baseline (speedup 1.0000x reference)
#include <cuda_runtime.h>
#include <math.h>

// ---------------- problem constants ----------------
#define NP   120000
#define DIM  256
#define BATCH 2
#define NH   8
#define DHD  32
#define NOUT 20
#define ZD 60
#define YD 45
#define XD 4
#define GQ 10800        // ZD*YD*XD
#define SQ 21600        // BATCH*GQ
#define ZE 12
#define YE 24
#define XE 2
#define GK 576          // ZE*YE*XE
#define SK 1152         // BATCH*GK
#define NF 42           // DIM/6
#define PEC 252         // 6*NF

// ---------------- scratch (device globals; no allocation allowed) ----------------
__device__ unsigned g_pool_key[SQ * DIM];
__device__ unsigned g_emb_key[SK * DIM];
__device__ int      g_mask_q[SQ];
__device__ int      g_mask_k[SK];
__device__ int      g_segq[NP];
__device__ int      g_segk[NP];
__device__ float    g_ef[(size_t)NP * DIM];      // 123 MB
__device__ int      g_arg[SK * DIM];
__device__ float    g_embc[SK * 3];
__device__ float    g_qin[(size_t)SQ * DIM];
__device__ float    g_kv[SK * DIM];
__device__ float    g_qp[(size_t)SQ * DIM];
__device__ float    g_kb[SK * DIM];
__device__ float    g_vb[SK * DIM];
__device__ float    g_S[(size_t)BATCH * NH * GQ * GK];   // 398 MB scores
__device__ float    g_oa[(size_t)SQ * DIM];
__device__ float    g_o2[(size_t)SQ * DIM];
__device__ float    g_mhca[(size_t)SQ * DIM];

// monotonic float<->u32 order-preserving encoding (bijective)
__device__ __forceinline__ unsigned fenc(float f) {
    unsigned u = __float_as_uint(f);
    return (u & 0x80000000u) ? ~u : (u | 0x80000000u);
}
__device__ __forceinline__ float fdec(unsigned k) {
    return __uint_as_float((k & 0x80000000u) ? (k ^ 0x80000000u) : ~k);
}

// ---------------- init ----------------
__global__ void init_k() {
    int i = blockIdx.x * 256 + threadIdx.x;
    if (i < SQ * DIM) g_pool_key[i] = 0u;
    if (i < SK * DIM) { g_emb_key[i] = 0u; g_arg[i] = -1; }
    if (i < SQ) g_mask_q[i] = 0;
    if (i < SK) g_mask_k[i] = 0;
}

// ---------------- per-point segment ids + occupancy masks ----------------
__global__ void prep_k(const int* __restrict__ ind) {
    int i = blockIdx.x * 256 + threadIdx.x;
    if (i >= NP) return;
    int b = ind[i * 4 + 0];
    int z = ind[i * 4 + 1];
    int y = ind[i * 4 + 2];
    int x = ind[i * 4 + 3];
    int sq = ((b * ZD + z / 8) * YD + y / 8) * XD + x / 8;
    int sk = ((b * ZE + z / 40) * YE + y / 15) * XE + x / 16;
    g_segq[i] = sq;
    g_segk[i] = sk;
    g_mask_q[sq] = 1;
    g_mask_k[sk] = 1;
}

// ---------------- generic 256-wide GEMM: C[M,256] = A[M,256] @ W[256,256] + b ----------------
// MODE 0: plain store to Cout
// MODE 1: atomicMax(fenc(val)) into keyOut[seg[m]*256+c]   (pool branch)
// MODE 2: store to Cout AND atomicMax into keyOut           (embedding branch)
template <int MODE>
__global__ void gemm_k(const float* __restrict__ A, const float* __restrict__ W,
                       const float* __restrict__ bias, float* __restrict__ Cout,
                       unsigned* __restrict__ keyOut, const int* __restrict__ seg, int M) {
    __shared__ float As[16][64];   // [k][m]
    __shared__ float Bs[16][64];   // [k][c]
    int t = threadIdx.x;
    int m0 = blockIdx.x * 64;
    int c0 = blockIdx.y * 64;
    int ty = t >> 4, tx = t & 15;
    int a_m = t >> 2;
    int a_k4 = (t & 3) * 4;
    int w_r = t >> 4;
    int w_c4 = (t & 15) * 4;
    float acc[4][4] = {};
    for (int k0 = 0; k0 < 256; k0 += 16) {
        float4 av = make_float4(0.f, 0.f, 0.f, 0.f);
        if (m0 + a_m < M)
            av = *(const float4*)&A[(size_t)(m0 + a_m) * 256 + k0 + a_k4];
        As[a_k4 + 0][a_m] = av.x;
        As[a_k4 + 1][a_m] = av.y;
        As[a_k4 + 2][a_m] = av.z;
        As[a_k4 + 3][a_m] = av.w;
        *(float4*)&Bs[w_r][w_c4] = *(const float4*)&W[(size_t)(k0 + w_r) * 256 + c0 + w_c4];
        __syncthreads();
#pragma unroll
        for (int kk = 0; kk < 16; kk++) {
            float4 a4 = *(float4*)&As[kk][ty * 4];
            float4 b4 = *(float4*)&Bs[kk][tx * 4];
            float a[4] = {a4.x, a4.y, a4.z, a4.w};
            float b[4] = {b4.x, b4.y, b4.z, b4.w};
#pragma unroll
            for (int i = 0; i < 4; i++)
#pragma unroll
                for (int j = 0; j < 4; j++) acc[i][j] = fmaf(a[i], b[j], acc[i][j]);
        }
        __syncthreads();
    }
#pragma unroll
    for (int i = 0; i < 4; i++) {
        int m = m0 + ty * 4 + i;
        if (m >= M) break;
        int sg = (MODE >= 1) ? seg[m] : 0;
#pragma unroll
        for (int j = 0; j < 4; j++) {
            int c = c0 + tx * 4 + j;
            float v = acc[i][j] + bias[c];
            if (MODE == 0) {
                Cout[(size_t)m * 256 + c] = v;
            } else {
                if (MODE == 2) Cout[(size_t)m * 256 + c] = v;
                atomicMax(&keyOut[sg * 256 + c], fenc(v));
            }
        }
    }
}

// ---------------- per-channel argmax (tie -> largest point index, like reference) ----------------
__global__ void argmax_k() {
    size_t idx = (size_t)blockIdx.x * 256 + threadIdx.x;
    if (idx >= (size_t)NP * DIM) return;
    int i = (int)(idx >> 8);
    int c = (int)(idx & 255);
    float v = g_ef[idx];
    int s = g_segk[i];
    if (v == fdec(g_emb_key[s * 256 + c])) atomicMax(&g_arg[s * 256 + c], i);
}

// ---------------- emb coords: mean over channels of winner downsampled coords * EP ----------------
__global__ void embc_k(const int* __restrict__ ind) {
    __shared__ float rz[256], ry[256], rx[256];
    int s = blockIdx.x;
    int t = threadIdx.x;
    int idx = g_arg[s * 256 + t];
    int i = idx < 0 ? 0 : idx;
    int z = ind[i * 4 + 1], y = ind[i * 4 + 2], x = ind[i * 4 + 3];
    rz[t] = (float)(z / 40);
    ry[t] = (float)(y / 15);
    rx[t] = (float)(x / 16);
    __syncthreads();
    for (int o = 128; o > 0; o >>= 1) {
        if (t < o) { rz[t] += rz[t + o]; ry[t] += ry[t + o]; rx[t] += rx[t + o]; }
        __syncthreads();
    }
    if (t == 0) {
        g_embc[s * 3 + 0] = rz[0] * (1.f / 256.f) * 40.f;
        g_embc[s * 3 + 1] = ry[0] * (1.f / 256.f) * 15.f;
        g_embc[s * 3 + 2] = rx[0] * (1.f / 256.f) * 16.f;
    }
}

// ---------------- sine positional encoding per channel ----------------
__device__ __forceinline__ float pe_val(float cz, float cy, float cx, int c) {
    if (c >= PEC) return 0.f;
    int axis = c / (2 * NF);
    int r = c - axis * (2 * NF);
    int j = r < NF ? r : r - NF;
    float coord = (axis == 0) ? cz : (axis == 1) ? cy : cx;
    float spd = (axis == 0) ? 480.f : (axis == 1) ? 360.f : 32.f;
    float tpow = powf(10000.f, (float)j * (1.f / (float)NF));
    float ang = coord / spd * 6.283185307179586f / tpow;
    return (r < NF) ? sinf(ang) : cosf(ang);
}

__global__ void buildq_k() {
    int s = blockIdx.x;
    int c = threadIdx.x;
    int rem = s % GQ;
    float cz = (float)((rem / (YD * XD)) * 8);
    float cy = (float)(((rem / XD) % YD) * 8);
    float cx = (float)((rem % XD) * 8);
    float base = g_mask_q[s] ? fdec(g_pool_key[(size_t)s * 256 + c]) : 0.f;
    g_qin[(size_t)s * 256 + c] = base + pe_val(cz, cy, cx, c);
}

__global__ void buildkv_k() {
    int s = blockIdx.x;
    int c = threadIdx.x;
    float cz = g_embc[s * 3 + 0];
    float cy = g_embc[s * 3 + 1];
    float cx = g_embc[s * 3 + 2];
    float base = g_mask_k[s] ? fdec(g_emb_key[s * 256 + c]) : 0.f;
    g_kv[s * 256 + c] = base + pe_val(cz, cy, cx, c);
}

// ---------------- attention scores: S[b,h,q,k] = (Q_h . K_h)/sqrt(32), masked ----------------
__global__ void scores_k(const float* __restrict__ qp, const float* __restrict__ kb,
                         const int* __restrict__ maskk, float* __restrict__ S) {
    __shared__ float Qs[32][64];  // [d][q]
    __shared__ float Ks[32][64];  // [d][k]
    int bh = blockIdx.z;
    int b = bh >> 3, h = bh & 7;
    int q0 = blockIdx.x * 64;
    int k0 = blockIdx.y * 64;
    int t = threadIdx.x;
#pragma unroll
    for (int i = 0; i < 2; i++) {
        int f = t * 2 + i;              // 0..511
        int row = f >> 3;
        int c4 = (f & 7) * 4;
        float4 v = make_float4(0.f, 0.f, 0.f, 0.f);
        if (q0 + row < GQ)
            v = *(const float4*)&qp[((size_t)(b * GQ + q0 + row)) * 256 + h * 32 + c4];
        Qs[c4 + 0][row] = v.x; Qs[c4 + 1][row] = v.y;
        Qs[c4 + 2][row] = v.z; Qs[c4 + 3][row] = v.w;
        float4 w = *(const float4*)&kb[((size_t)(b * GK + k0 + row)) * 256 + h * 32 + c4];
        Ks[c4 + 0][row] = w.x; Ks[c4 + 1][row] = w.y;
        Ks[c4 + 2][row] = w.z; Ks[c4 + 3][row] = w.w;
    }
    __syncthreads();
    int ty = t >> 4, tx = t & 15;
    float acc[4][4] = {};
#pragma unroll
    for (int kk = 0; kk < 32; kk++) {
        float4 a4 = *(float4*)&Qs[kk][ty * 4];
        float4 b4 = *(float4*)&Ks[kk][tx * 4];
        float a[4] = {a4.x, a4.y, a4.z, a4.w};
        float bb[4] = {b4.x, b4.y, b4.z, b4.w};
#pragma unroll
        for (int i = 0; i < 4; i++)
#pragma unroll
            for (int j = 0; j < 4; j++) acc[i][j] = fmaf(a[i], bb[j], acc[i][j]);
    }
    const float scale = 0.1767766952966369f;  // 1/sqrt(32)
#pragma unroll
    for (int i = 0; i < 4; i++) {
        int q = q0 + ty * 4 + i;
        if (q >= GQ) break;
#pragma unroll
        for (int j = 0; j < 4; j++) {
            int k = k0 + tx * 4 + j;
            float v = maskk[b * GK + k] ? acc[i][j] * scale : -1e9f;
            S[((size_t)bh * GQ + q) * GK + k] = v;
        }
    }
}

// ---------------- softmax over 576 keys, warp per row ----------------
__global__ void softmax_k(float* __restrict__ S) {
    int row = blockIdx.x * 8 + (threadIdx.x >> 5);
    int lane = threadIdx.x & 31;
    float* p = &S[(size_t)row * GK];
    float vals[18];
    float mx = -INFINITY;
#pragma unroll
    for (int i = 0; i < 18; i++) { vals[i] = p[lane + 32 * i]; mx = fmaxf(mx, vals[i]); }
#pragma unroll
    for (int o = 16; o; o >>= 1) mx = fmaxf(mx, __shfl_xor_sync(0xFFFFFFFFu, mx, o));
    float sum = 0.f;
#pragma unroll
    for (int i = 0; i < 18; i++) { vals[i] = __expf(vals[i] - mx); sum += vals[i]; }
#pragma unroll
    for (int o = 16; o; o >>= 1) sum += __shfl_xor_sync(0xFFFFFFFFu, sum, o);
    float inv = 1.f / sum;
#pragma unroll
    for (int i = 0; i < 18; i++) p[lane + 32 * i] = vals[i] * inv;
}

// ---------------- attn @ V ----------------
__global__ void av_k(const float* __restrict__ S, const float* __restrict__ vb,
                     float* __restrict__ oa) {
    __shared__ float Ss[64][64];  // [q][k]
    __shared__ float Vs[64][32];  // [k][d]
    int bh = blockIdx.y;
    int b = bh >> 3, h = bh & 7;
    int q0 = blockIdx.x * 64;
    int t = threadIdx.x;
    int ty = t >> 5, tx = t & 31;
    float acc[8] = {};
    for (int kc = 0; kc < GK; kc += 64) {
#pragma unroll
        for (int i = 0; i < 4; i++) {
            int f = t + 256 * i;
            int row = f >> 4;
            int c4 = (f & 15) * 4;
            float4 v = make_float4(0.f, 0.f, 0.f, 0.f);
            if (q0 + row < GQ)
                v = *(const float4*)&S[((size_t)bh * GQ + q0 + row) * GK + kc + c4];
            *(float4*)&Ss[row][c4] = v;
        }
#pragma unroll
        for (int i = 0; i < 2; i++) {
            int f = t + 256 * i;
            int row = f >> 3;
            int c4 = (f & 7) * 4;
            *(float4*)&Vs[row][c4] =
                *(const float4*)&vb[((size_t)(b * GK + kc + row)) * 256 + h * 32 + c4];
        }
        __syncthreads();
#pragma unroll
        for (int kk = 0; kk < 64; kk += 4) {
            float v0 = Vs[kk + 0][tx];
            float v1 = Vs[kk + 1][tx];
            float v2 = Vs[kk + 2][tx];
            float v3 = Vs[kk + 3][tx];
#pragma unroll
            for (int r = 0; r < 8; r++) {
                float4 s4 = *(float4*)&Ss[ty * 8 + r][kk];
                acc[r] = fmaf(s4.x, v0, acc[r]);
                acc[r] = fmaf(s4.y, v1, acc[r]);
                acc[r] = fmaf(s4.z, v2, acc[r]);
                acc[r] = fmaf(s4.w, v3, acc[r]);
            }
        }
        __syncthreads();
    }
#pragma unroll
    for (int r = 0; r < 8; r++) {
        int q = q0 + ty * 8 + r;
        if (q < GQ) oa[((size_t)(b * GQ + q)) * 256 + h * 32 + tx] = acc[r];
    }
}

// ---------------- residual + LayerNorm ----------------
__global__ void ln_k(const float* __restrict__ qin, const float* __restrict__ o2,
                     const float* __restrict__ g, const float* __restrict__ bb,
                     float* __restrict__ out) {
    __shared__ float red[256];
    __shared__ float mu_s, var_s;
    int r = blockIdx.x;
    int c = threadIdx.x;
    float h = qin[(size_t)r * 256 + c] + o2[(size_t)r * 256 + c];
    red[c] = h;
    __syncthreads();
    for (int o = 128; o > 0; o >>= 1) {
        if (c < o) red[c] += red[c + o];
        __syncthreads();
    }
    if (c == 0) mu_s = red[0] * (1.f / 256.f);
    __syncthreads();
    float d = h - mu_s;
    red[c] = d * d;
    __syncthreads();
    for (int o = 128; o > 0; o >>= 1) {
        if (c < o) red[c] += red[c + o];
        __syncthreads();
    }
    if (c == 0) var_s = red[0] * (1.f / 256.f);
    __syncthreads();
    out[(size_t)r * 256 + c] = d * rsqrtf(var_s + 1e-5f) * g[c] + bb[c];
}

// ---------------- final gather + seg head ----------------
__global__ void head_k(const float* __restrict__ feat, const float* __restrict__ Wseg,
                       const float* __restrict__ bseg, float* __restrict__ out) {
    __shared__ float Ws[256 * NOUT];
    int t = threadIdx.x;
    for (int i = t; i < 256 * NOUT; i += 256) Ws[i] = Wseg[i];
    __syncthreads();
    int p = blockIdx.x * 8 + (t >> 5);
    int lane = t & 31;
    int sg = g_segq[p];
    float v[8];
#pragma unroll
    for (int r = 0; r < 8; r++) {
        int c = lane + 32 * r;
        v[r] = feat[(size_t)p * 256 + c] + g_mhca[(size_t)sg * 256 + c];
    }
#pragma unroll
    for (int j = 0; j < NOUT; j++) {
        float s = 0.f;
#pragma unroll
        for (int r = 0; r < 8; r++) s = fmaf(v[r], Ws[(lane + 32 * r) * NOUT + j], s);
#pragma unroll
        for (int o = 16; o; o >>= 1) s += __shfl_xor_sync(0xFFFFFFFFu, s, o);
        if (lane == 0) out[(size_t)p * NOUT + j] = s + bseg[j];
    }
}

// ---------------- host launch ----------------
static void* sym_addr(const void* symbol) {
    void* p = nullptr;
    cudaGetSymbolAddress(&p, symbol);
    return p;
}

extern "C" void kernel_launch(void* const* d_in, const int* in_sizes, int n_in,
                              void* d_out, int out_size) {
    const float* feat  = (const float*)d_in[0];
    const float* Wpool = (const float*)d_in[1];
    const float* bpool = (const float*)d_in[2];
    const float* Wemb  = (const float*)d_in[3];
    const float* bemb  = (const float*)d_in[4];
    const float* Wq    = (const float*)d_in[5];
    const float* bq    = (const float*)d_in[6];
    const float* Wk    = (const float*)d_in[7];
    const float* bk    = (const float*)d_in[8];
    const float* Wv    = (const float*)d_in[9];
    const float* bv    = (const float*)d_in[10];
    const float* Wo    = (const float*)d_in[11];
    const float* bo    = (const float*)d_in[12];
    const float* lng   = (const float*)d_in[13];
    const float* lnb   = (const float*)d_in[14];
    const float* Wseg  = (const float*)d_in[15];
    const float* bseg  = (const float*)d_in[16];
    const int*   ind   = (const int*)d_in[17];
    float* out = (float*)d_out;

    unsigned* p_pool_key = (unsigned*)sym_addr(g_pool_key);
    unsigned* p_emb_key  = (unsigned*)sym_addr(g_emb_key);
    int*      p_segq     = (int*)sym_addr(g_segq);
    int*      p_segk     = (int*)sym_addr(g_segk);
    int*      p_mask_k   = (int*)sym_addr(g_mask_k);
    float*    p_ef       = (float*)sym_addr(g_ef);
    float*    p_qin      = (float*)sym_addr(g_qin);
    float*    p_kv       = (float*)sym_addr(g_kv);
    float*    p_qp       = (float*)sym_addr(g_qp);
    float*    p_kb       = (float*)sym_addr(g_kb);
    float*    p_vb       = (float*)sym_addr(g_vb);
    float*    p_S        = (float*)sym_addr(g_S);
    float*    p_oa       = (float*)sym_addr(g_oa);
    float*    p_o2       = (float*)sym_addr(g_o2);
    float*    p_mhca     = (float*)sym_addr(g_mhca);

    // 1. init scratch
    init_k<<<(SQ * DIM + 255) / 256, 256>>>();
    // 2. segment ids + masks
    prep_k<<<(NP + 255) / 256, 256>>>(ind);
    // 3. pool branch: GEMM + scatter-max
    gemm_k<1><<<dim3(NP / 64, 4), 256>>>(feat, Wpool, bpool, nullptr, p_pool_key, p_segq, NP);
    // 4. emb branch: GEMM + store + scatter-max
    gemm_k<2><<<dim3(NP / 64, 4), 256>>>(feat, Wemb, bemb, p_ef, p_emb_key, p_segk, NP);
    // 5. per-channel argmax
    argmax_k<<<(NP * DIM) / 256, 256>>>();
    // 6. winner coords
    embc_k<<<SK, 256>>>(ind);
    // 7. PE-added grids
    buildq_k<<<SQ, 256>>>();
    buildkv_k<<<SK, 256>>>();
    // 8. projections
    gemm_k<0><<<dim3((SQ + 63) / 64, 4), 256>>>(p_qin, Wq, bq, p_qp, nullptr, nullptr, SQ);
    gemm_k<0><<<dim3(SK / 64, 4), 256>>>(p_kv, Wk, bk, p_kb, nullptr, nullptr, SK);
    gemm_k<0><<<dim3(SK / 64, 4), 256>>>(p_kv, Wv, bv, p_vb, nullptr, nullptr, SK);
    // 9. attention
    scores_k<<<dim3((GQ + 63) / 64, GK / 64, BATCH * NH), 256>>>(p_qp, p_kb, p_mask_k, p_S);
    softmax_k<<<(BATCH * NH * GQ) / 8, 256>>>(p_S);
    av_k<<<dim3((GQ + 63) / 64, BATCH * NH), 256>>>(p_S, p_vb, p_oa);
    // 10. output projection + residual + LN
    gemm_k<0><<<dim3((SQ + 63) / 64, 4), 256>>>(p_oa, Wo, bo, p_o2, nullptr, nullptr, SQ);
    ln_k<<<SQ, 256>>>(p_qin, p_o2, lng, lnb, p_mhca);
    // 11. gather + seg head
    head_k<<<NP / 8, 256>>>(feat, Wseg, bseg, out);
}

// round 3
// speedup vs baseline: 1.2718x; 1.2718x over previous
#include <cuda_runtime.h>
#include <cuda_bf16.h>
#include <math.h>
#include <stdint.h>

// ---------------- problem constants ----------------
#define NP   120000
#define DIM  256
#define BATCH 2
#define NH   8
#define NOUT 20
#define ZD 60
#define YD 45
#define XD 4
#define GQ 10800        // ZD*YD*XD
#define SQ 21600        // BATCH*GQ
#define ZE 12
#define YE 24
#define XE 2
#define GK 576          // ZE*YE*XE
#define SK 1152         // BATCH*GK
#define NF 42           // DIM/6
#define PEC 252         // 6*NF

// ---------------- scratch (device globals; no allocation allowed) ----------------
__device__ unsigned g_pool_key[SQ * DIM];
__device__ unsigned g_emb_key[SK * DIM];
__device__ int      g_mask_q[SQ];
__device__ int      g_mask_k[SK];
__device__ int      g_segq[NP];
__device__ int      g_segk[NP];
__device__ float    g_ef[(size_t)NP * DIM];      // 123 MB
__device__ int      g_arg[SK * DIM];
__device__ float    g_embc[SK * 3];
__device__ float    g_qin[(size_t)SQ * DIM];
__device__ float    g_kv[SK * DIM];
__device__ float    g_qp[(size_t)SQ * DIM];
__device__ float    g_kb[SK * DIM];
__device__ float    g_vb[SK * DIM];
__device__ float    g_S[(size_t)BATCH * NH * GQ * GK];   // scores
__device__ float    g_oa[(size_t)SQ * DIM];
__device__ float    g_o2[(size_t)SQ * DIM];
__device__ float    g_mhca[(size_t)SQ * DIM];

// monotonic float<->u32 order-preserving encoding (bijective)
__device__ __forceinline__ unsigned fenc(float f) {
    unsigned u = __float_as_uint(f);
    return (u & 0x80000000u) ? ~u : (u | 0x80000000u);
}
__device__ __forceinline__ float fdec(unsigned k) {
    return __uint_as_float((k & 0x80000000u) ? (k ^ 0x80000000u) : ~k);
}

// ================= warp MMA helpers (baseline sm_80+ features only) =================
__device__ __forceinline__ uint32_t sptr(const void* p) {
    return (uint32_t)__cvta_generic_to_shared(p);
}

#define LDSM_X4(r, addr) \
    asm volatile("ldmatrix.sync.aligned.m8n8.x4.shared.b16 {%0,%1,%2,%3}, [%4];" \
        : "=r"((r)[0]), "=r"((r)[1]), "=r"((r)[2]), "=r"((r)[3]) : "r"(addr))

#define LDSM_X4_T(r, addr) \
    asm volatile("ldmatrix.sync.aligned.m8n8.x4.trans.shared.b16 {%0,%1,%2,%3}, [%4];" \
        : "=r"((r)[0]), "=r"((r)[1]), "=r"((r)[2]), "=r"((r)[3]) : "r"(addr))

__device__ __forceinline__ void mma16816(float* c, const uint32_t* a, uint32_t b0, uint32_t b1) {
    asm volatile(
        "mma.sync.aligned.m16n8k16.row.col.f32.bf16.bf16.f32 "
        "{%0,%1,%2,%3}, {%4,%5,%6,%7}, {%8,%9}, {%0,%1,%2,%3};"
        : "+f"(c[0]), "+f"(c[1]), "+f"(c[2]), "+f"(c[3])
        : "r"(a[0]), "r"(a[1]), "r"(a[2]), "r"(a[3]), "r"(b0), "r"(b1));
}

__device__ __forceinline__ void split_bf16(float v, __nv_bfloat16& h, __nv_bfloat16& l) {
    h = __float2bfloat16(v);
    l = __float2bfloat16(v - __bfloat162float(h));
}

// ================= bf16x3 split-precision MMA GEMM ==================
// C[M,256] = A[M,256] @ W[256,256] + bias, computed as Ah*Bh + Ah*Bl + Al*Bh.
// CTA tile 128(m) x 64(n); 256 threads = 8 warps as 2(m) x 4(n), warp tile 64x16.
// MODE 0: store Cout; MODE 1: atomicMax scatter only; MODE 2: store + scatter.
#define APAD 40   // 32 k + 8 pad (80B rows: conflict-free ldmatrix)
#define BPAD 72   // 64 n + 8 pad (144B rows: conflict-free ldmatrix.trans)
template <int MODE>
__global__ __launch_bounds__(256, 2) void mma_gemm(
    const float* __restrict__ A, const float* __restrict__ W,
    const float* __restrict__ bias, float* __restrict__ Cout,
    unsigned* __restrict__ keyOut, const int* __restrict__ segArr, int M)
{
    __shared__ __align__(16) __nv_bfloat16 sA[2][128][APAD];  // [hi/lo][m][k]
    __shared__ __align__(16) __nv_bfloat16 sB[2][32][BPAD];   // [hi/lo][k][n]

    int t = threadIdx.x;
    int wid = t >> 5, lane = t & 31;
    int wm = wid >> 2;            // 0..1  -> m offset wm*64
    int wn = wid & 3;             // 0..3  -> n offset wn*16
    int m0 = blockIdx.x * 128;
    int c0 = blockIdx.y * 64;

    float acc[4][2][4] = {};      // [m-tile 16][n-tile 8][frag]

    // per-thread load indices
    int a_row = t >> 1;               // 0..127
    int a_cs  = (t & 1) * 16;         // 0 or 16
    int b_k   = t >> 3;               // 0..31
    int b_ns  = (t & 7) * 8;          // 0..56

    for (int ch = 0; ch < 8; ch++) {
        int k0 = ch * 32;
        // ---- load + split A chunk [128 x 32] ----
        {
            bool inb = (m0 + a_row) < M;
            const float* ap = &A[(size_t)(m0 + a_row) * 256 + k0 + a_cs];
#pragma unroll
            for (int q = 0; q < 4; q++) {
                float4 v = inb ? *(const float4*)(ap + q * 4)
                               : make_float4(0.f, 0.f, 0.f, 0.f);
                __nv_bfloat16 hx, lx, hy, ly, hz, lz, hw, lw;
                split_bf16(v.x, hx, lx); split_bf16(v.y, hy, ly);
                split_bf16(v.z, hz, lz); split_bf16(v.w, hw, lw);
                __nv_bfloat162* ph = (__nv_bfloat162*)&sA[0][a_row][a_cs + q * 4];
                ph[0] = __nv_bfloat162(hx, hy);
                ph[1] = __nv_bfloat162(hz, hw);
                __nv_bfloat162* pl = (__nv_bfloat162*)&sA[1][a_row][a_cs + q * 4];
                pl[0] = __nv_bfloat162(lx, ly);
                pl[1] = __nv_bfloat162(lz, lw);
            }
        }
        // ---- load + split B chunk [32 x 64] (W rows k0..k0+31, cols c0..c0+63) ----
        {
            const float* wp = &W[(size_t)(k0 + b_k) * 256 + c0 + b_ns];
#pragma unroll
            for (int q = 0; q < 2; q++) {
                float4 v = *(const float4*)(wp + q * 4);
                __nv_bfloat16 hx, lx, hy, ly, hz, lz, hw, lw;
                split_bf16(v.x, hx, lx); split_bf16(v.y, hy, ly);
                split_bf16(v.z, hz, lz); split_bf16(v.w, hw, lw);
                __nv_bfloat162* ph = (__nv_bfloat162*)&sB[0][b_k][b_ns + q * 4];
                ph[0] = __nv_bfloat162(hx, hy);
                ph[1] = __nv_bfloat162(hz, hw);
                __nv_bfloat162* pl = (__nv_bfloat162*)&sB[1][b_k][b_ns + q * 4];
                pl[0] = __nv_bfloat162(lx, ly);
                pl[1] = __nv_bfloat162(lz, lw);
            }
        }
        __syncthreads();

        // ---- compute: two k16 steps ----
#pragma unroll
        for (int ks = 0; ks < 2; ks++) {
            int arow = wm * 64 + (lane & 15);
            int akc = ks * 16 + ((lane & 16) ? 8 : 0);
            int bkr = ks * 16 + (lane & 15);
            int bnc = wn * 16 + ((lane & 16) ? 8 : 0);

            uint32_t af[4][4];
            uint32_t bh[4], bl[4];
#pragma unroll
            for (int mt = 0; mt < 4; mt++)
                LDSM_X4(af[mt], sptr(&sA[0][arow + mt * 16][akc]));
            LDSM_X4_T(bh, sptr(&sB[0][bkr][bnc]));
            LDSM_X4_T(bl, sptr(&sB[1][bkr][bnc]));

            // Ah*Bh + Ah*Bl
#pragma unroll
            for (int mt = 0; mt < 4; mt++) {
#pragma unroll
                for (int nt = 0; nt < 2; nt++) {
                    mma16816(acc[mt][nt], af[mt], bh[nt * 2], bh[nt * 2 + 1]);
                    mma16816(acc[mt][nt], af[mt], bl[nt * 2], bl[nt * 2 + 1]);
                }
            }
            // Al*Bh
#pragma unroll
            for (int mt = 0; mt < 4; mt++)
                LDSM_X4(af[mt], sptr(&sA[1][arow + mt * 16][akc]));
#pragma unroll
            for (int mt = 0; mt < 4; mt++) {
#pragma unroll
                for (int nt = 0; nt < 2; nt++)
                    mma16816(acc[mt][nt], af[mt], bh[nt * 2], bh[nt * 2 + 1]);
            }
        }
        __syncthreads();
    }

    // ---- epilogue: bias + store / scatter-max ----
    int g = lane >> 2, tid4 = lane & 3;
#pragma unroll
    for (int mt = 0; mt < 4; mt++) {
#pragma unroll
        for (int nt = 0; nt < 2; nt++) {
            int coln = c0 + wn * 16 + nt * 8 + tid4 * 2;
            float b0 = bias[coln], b1 = bias[coln + 1];
#pragma unroll
            for (int half = 0; half < 2; half++) {
                int m = m0 + wm * 64 + mt * 16 + g + half * 8;
                if (m >= M) continue;
                float v0 = acc[mt][nt][half * 2 + 0] + b0;
                float v1 = acc[mt][nt][half * 2 + 1] + b1;
                if (MODE == 0) {
                    Cout[(size_t)m * 256 + coln]     = v0;
                    Cout[(size_t)m * 256 + coln + 1] = v1;
                } else {
                    if (MODE == 2) {
                        Cout[(size_t)m * 256 + coln]     = v0;
                        Cout[(size_t)m * 256 + coln + 1] = v1;
                    }
                    int sg = segArr[m];
                    atomicMax(&keyOut[sg * 256 + coln],     fenc(v0));
                    atomicMax(&keyOut[sg * 256 + coln + 1], fenc(v1));
                }
            }
        }
    }
}

// ---------------- init ----------------
__global__ void init_k() {
    int i = blockIdx.x * 256 + threadIdx.x;
    if (i < SQ * DIM) g_pool_key[i] = 0u;
    if (i < SK * DIM) { g_emb_key[i] = 0u; g_arg[i] = -1; }
    if (i < SQ) g_mask_q[i] = 0;
    if (i < SK) g_mask_k[i] = 0;
}

// ---------------- per-point segment ids + occupancy masks ----------------
__global__ void prep_k(const int* __restrict__ ind) {
    int i = blockIdx.x * 256 + threadIdx.x;
    if (i >= NP) return;
    int b = ind[i * 4 + 0];
    int z = ind[i * 4 + 1];
    int y = ind[i * 4 + 2];
    int x = ind[i * 4 + 3];
    int sq = ((b * ZD + z / 8) * YD + y / 8) * XD + x / 8;
    int sk = ((b * ZE + z / 40) * YE + y / 15) * XE + x / 16;
    g_segq[i] = sq;
    g_segk[i] = sk;
    g_mask_q[sq] = 1;
    g_mask_k[sk] = 1;
}

// ---------------- per-channel argmax (tie -> largest point index) ----------------
__global__ void argmax_k() {
    size_t idx = (size_t)blockIdx.x * 256 + threadIdx.x;
    if (idx >= (size_t)NP * DIM) return;
    int i = (int)(idx >> 8);
    int c = (int)(idx & 255);
    float v = g_ef[idx];
    int s = g_segk[i];
    if (v == fdec(g_emb_key[s * 256 + c])) atomicMax(&g_arg[s * 256 + c], i);
}

// ---------------- emb coords ----------------
__global__ void embc_k(const int* __restrict__ ind) {
    __shared__ float rz[256], ry[256], rx[256];
    int s = blockIdx.x;
    int t = threadIdx.x;
    int idx = g_arg[s * 256 + t];
    int i = idx < 0 ? 0 : idx;
    int z = ind[i * 4 + 1], y = ind[i * 4 + 2], x = ind[i * 4 + 3];
    rz[t] = (float)(z / 40);
    ry[t] = (float)(y / 15);
    rx[t] = (float)(x / 16);
    __syncthreads();
    for (int o = 128; o > 0; o >>= 1) {
        if (t < o) { rz[t] += rz[t + o]; ry[t] += ry[t + o]; rx[t] += rx[t + o]; }
        __syncthreads();
    }
    if (t == 0) {
        g_embc[s * 3 + 0] = rz[0] * (1.f / 256.f) * 40.f;
        g_embc[s * 3 + 1] = ry[0] * (1.f / 256.f) * 15.f;
        g_embc[s * 3 + 2] = rx[0] * (1.f / 256.f) * 16.f;
    }
}

// ---------------- sine positional encoding ----------------
__device__ __forceinline__ float pe_val(float cz, float cy, float cx, int c) {
    if (c >= PEC) return 0.f;
    int axis = c / (2 * NF);
    int r = c - axis * (2 * NF);
    int j = r < NF ? r : r - NF;
    float coord = (axis == 0) ? cz : (axis == 1) ? cy : cx;
    float spd = (axis == 0) ? 480.f : (axis == 1) ? 360.f : 32.f;
    float tpow = powf(10000.f, (float)j * (1.f / (float)NF));
    float ang = coord / spd * 6.283185307179586f / tpow;
    return (r < NF) ? sinf(ang) : cosf(ang);
}

__global__ void buildq_k() {
    int s = blockIdx.x;
    int c = threadIdx.x;
    int rem = s % GQ;
    float cz = (float)((rem / (YD * XD)) * 8);
    float cy = (float)(((rem / XD) % YD) * 8);
    float cx = (float)((rem % XD) * 8);
    float base = g_mask_q[s] ? fdec(g_pool_key[(size_t)s * 256 + c]) : 0.f;
    g_qin[(size_t)s * 256 + c] = base + pe_val(cz, cy, cx, c);
}

__global__ void buildkv_k() {
    int s = blockIdx.x;
    int c = threadIdx.x;
    float cz = g_embc[s * 3 + 0];
    float cy = g_embc[s * 3 + 1];
    float cx = g_embc[s * 3 + 2];
    float base = g_mask_k[s] ? fdec(g_emb_key[s * 256 + c]) : 0.f;
    g_kv[s * 256 + c] = base + pe_val(cz, cy, cx, c);
}

// ---------------- attention scores ----------------
__global__ void scores_k(const float* __restrict__ qp, const float* __restrict__ kb,
                         const int* __restrict__ maskk, float* __restrict__ S) {
    __shared__ float Qs[32][64];
    __shared__ float Ks[32][64];
    int bh = blockIdx.z;
    int b = bh >> 3, h = bh & 7;
    int q0 = blockIdx.x * 64;
    int k0 = blockIdx.y * 64;
    int t = threadIdx.x;
#pragma unroll
    for (int i = 0; i < 2; i++) {
        int f = t * 2 + i;
        int row = f >> 3;
        int c4 = (f & 7) * 4;
        float4 v = make_float4(0.f, 0.f, 0.f, 0.f);
        if (q0 + row < GQ)
            v = *(const float4*)&qp[((size_t)(b * GQ + q0 + row)) * 256 + h * 32 + c4];
        Qs[c4 + 0][row] = v.x; Qs[c4 + 1][row] = v.y;
        Qs[c4 + 2][row] = v.z; Qs[c4 + 3][row] = v.w;
        float4 w = *(const float4*)&kb[((size_t)(b * GK + k0 + row)) * 256 + h * 32 + c4];
        Ks[c4 + 0][row] = w.x; Ks[c4 + 1][row] = w.y;
        Ks[c4 + 2][row] = w.z; Ks[c4 + 3][row] = w.w;
    }
    __syncthreads();
    int ty = t >> 4, tx = t & 15;
    float acc[4][4] = {};
#pragma unroll
    for (int kk = 0; kk < 32; kk++) {
        float4 a4 = *(float4*)&Qs[kk][ty * 4];
        float4 b4 = *(float4*)&Ks[kk][tx * 4];
        float a[4] = {a4.x, a4.y, a4.z, a4.w};
        float bb[4] = {b4.x, b4.y, b4.z, b4.w};
#pragma unroll
        for (int i = 0; i < 4; i++)
#pragma unroll
            for (int j = 0; j < 4; j++) acc[i][j] = fmaf(a[i], bb[j], acc[i][j]);
    }
    const float scale = 0.1767766952966369f;
#pragma unroll
    for (int i = 0; i < 4; i++) {
        int q = q0 + ty * 4 + i;
        if (q >= GQ) break;
#pragma unroll
        for (int j = 0; j < 4; j++) {
            int k = k0 + tx * 4 + j;
            float v = maskk[b * GK + k] ? acc[i][j] * scale : -1e9f;
            S[((size_t)bh * GQ + q) * GK + k] = v;
        }
    }
}

// ---------------- softmax over 576 keys ----------------
__global__ void softmax_k(float* __restrict__ S) {
    int row = blockIdx.x * 8 + (threadIdx.x >> 5);
    int lane = threadIdx.x & 31;
    float* p = &S[(size_t)row * GK];
    float vals[18];
    float mx = -INFINITY;
#pragma unroll
    for (int i = 0; i < 18; i++) { vals[i] = p[lane + 32 * i]; mx = fmaxf(mx, vals[i]); }
#pragma unroll
    for (int o = 16; o; o >>= 1) mx = fmaxf(mx, __shfl_xor_sync(0xFFFFFFFFu, mx, o));
    float sum = 0.f;
#pragma unroll
    for (int i = 0; i < 18; i++) { vals[i] = __expf(vals[i] - mx); sum += vals[i]; }
#pragma unroll
    for (int o = 16; o; o >>= 1) sum += __shfl_xor_sync(0xFFFFFFFFu, sum, o);
    float inv = 1.f / sum;
#pragma unroll
    for (int i = 0; i < 18; i++) p[lane + 32 * i] = vals[i] * inv;
}

// ---------------- attn @ V ----------------
__global__ void av_k(const float* __restrict__ S, const float* __restrict__ vb,
                     float* __restrict__ oa) {
    __shared__ float Ss[64][64];
    __shared__ float Vs[64][32];
    int bh = blockIdx.y;
    int b = bh >> 3, h = bh & 7;
    int q0 = blockIdx.x * 64;
    int t = threadIdx.x;
    int ty = t >> 5, tx = t & 31;
    float acc[8] = {};
    for (int kc = 0; kc < GK; kc += 64) {
#pragma unroll
        for (int i = 0; i < 4; i++) {
            int f = t + 256 * i;
            int row = f >> 4;
            int c4 = (f & 15) * 4;
            float4 v = make_float4(0.f, 0.f, 0.f, 0.f);
            if (q0 + row < GQ)
                v = *(const float4*)&S[((size_t)bh * GQ + q0 + row) * GK + kc + c4];
            *(float4*)&Ss[row][c4] = v;
        }
#pragma unroll
        for (int i = 0; i < 2; i++) {
            int f = t + 256 * i;
            int row = f >> 3;
            int c4 = (f & 7) * 4;
            *(float4*)&Vs[row][c4] =
                *(const float4*)&vb[((size_t)(b * GK + kc + row)) * 256 + h * 32 + c4];
        }
        __syncthreads();
#pragma unroll
        for (int kk = 0; kk < 64; kk += 4) {
            float v0 = Vs[kk + 0][tx];
            float v1 = Vs[kk + 1][tx];
            float v2 = Vs[kk + 2][tx];
            float v3 = Vs[kk + 3][tx];
#pragma unroll
            for (int r = 0; r < 8; r++) {
                float4 s4 = *(float4*)&Ss[ty * 8 + r][kk];
                acc[r] = fmaf(s4.x, v0, acc[r]);
                acc[r] = fmaf(s4.y, v1, acc[r]);
                acc[r] = fmaf(s4.z, v2, acc[r]);
                acc[r] = fmaf(s4.w, v3, acc[r]);
            }
        }
        __syncthreads();
    }
#pragma unroll
    for (int r = 0; r < 8; r++) {
        int q = q0 + ty * 8 + r;
        if (q < GQ) oa[((size_t)(b * GQ + q)) * 256 + h * 32 + tx] = acc[r];
    }
}

// ---------------- residual + LayerNorm ----------------
__global__ void ln_k(const float* __restrict__ qin, const float* __restrict__ o2,
                     const float* __restrict__ g, const float* __restrict__ bb,
                     float* __restrict__ out) {
    __shared__ float red[256];
    __shared__ float mu_s, var_s;
    int r = blockIdx.x;
    int c = threadIdx.x;
    float h = qin[(size_t)r * 256 + c] + o2[(size_t)r * 256 + c];
    red[c] = h;
    __syncthreads();
    for (int o = 128; o > 0; o >>= 1) {
        if (c < o) red[c] += red[c + o];
        __syncthreads();
    }
    if (c == 0) mu_s = red[0] * (1.f / 256.f);
    __syncthreads();
    float d = h - mu_s;
    red[c] = d * d;
    __syncthreads();
    for (int o = 128; o > 0; o >>= 1) {
        if (c < o) red[c] += red[c + o];
        __syncthreads();
    }
    if (c == 0) var_s = red[0] * (1.f / 256.f);
    __syncthreads();
    out[(size_t)r * 256 + c] = d * rsqrtf(var_s + 1e-5f) * g[c] + bb[c];
}

// ---------------- final gather + seg head ----------------
__global__ void head_k(const float* __restrict__ feat, const float* __restrict__ Wseg,
                       const float* __restrict__ bseg, float* __restrict__ out) {
    __shared__ float Ws[256 * NOUT];
    int t = threadIdx.x;
    for (int i = t; i < 256 * NOUT; i += 256) Ws[i] = Wseg[i];
    __syncthreads();
    int p = blockIdx.x * 8 + (t >> 5);
    int lane = t & 31;
    int sg = g_segq[p];
    float v[8];
#pragma unroll
    for (int r = 0; r < 8; r++) {
        int c = lane + 32 * r;
        v[r] = feat[(size_t)p * 256 + c] + g_mhca[(size_t)sg * 256 + c];
    }
#pragma unroll
    for (int j = 0; j < NOUT; j++) {
        float s = 0.f;
#pragma unroll
        for (int r = 0; r < 8; r++) s = fmaf(v[r], Ws[(lane + 32 * r) * NOUT + j], s);
#pragma unroll
        for (int o = 16; o; o >>= 1) s += __shfl_xor_sync(0xFFFFFFFFu, s, o);
        if (lane == 0) out[(size_t)p * NOUT + j] = s + bseg[j];
    }
}

// ---------------- host launch ----------------
static void* sym_addr(const void* symbol) {
    void* p = nullptr;
    cudaGetSymbolAddress(&p, symbol);
    return p;
}

extern "C" void kernel_launch(void* const* d_in, const int* in_sizes, int n_in,
                              void* d_out, int out_size) {
    const float* feat  = (const float*)d_in[0];
    const float* Wpool = (const float*)d_in[1];
    const float* bpool = (const float*)d_in[2];
    const float* Wemb  = (const float*)d_in[3];
    const float* bemb  = (const float*)d_in[4];
    const float* Wq    = (const float*)d_in[5];
    const float* bq    = (const float*)d_in[6];
    const float* Wk    = (const float*)d_in[7];
    const float* bk    = (const float*)d_in[8];
    const float* Wv    = (const float*)d_in[9];
    const float* bv    = (const float*)d_in[10];
    const float* Wo    = (const float*)d_in[11];
    const float* bo    = (const float*)d_in[12];
    const float* lng   = (const float*)d_in[13];
    const float* lnb   = (const float*)d_in[14];
    const float* Wseg  = (const float*)d_in[15];
    const float* bseg  = (const float*)d_in[16];
    const int*   ind   = (const int*)d_in[17];
    float* out = (float*)d_out;

    unsigned* p_pool_key = (unsigned*)sym_addr(g_pool_key);
    unsigned* p_emb_key  = (unsigned*)sym_addr(g_emb_key);
    int*      p_segq     = (int*)sym_addr(g_segq);
    int*      p_segk     = (int*)sym_addr(g_segk);
    int*      p_mask_k   = (int*)sym_addr(g_mask_k);
    float*    p_ef       = (float*)sym_addr(g_ef);
    float*    p_qin      = (float*)sym_addr(g_qin);
    float*    p_kv       = (float*)sym_addr(g_kv);
    float*    p_qp       = (float*)sym_addr(g_qp);
    float*    p_kb       = (float*)sym_addr(g_kb);
    float*    p_vb       = (float*)sym_addr(g_vb);
    float*    p_S        = (float*)sym_addr(g_S);
    float*    p_oa       = (float*)sym_addr(g_oa);
    float*    p_o2       = (float*)sym_addr(g_o2);
    float*    p_mhca     = (float*)sym_addr(g_mhca);

    // 1. init scratch
    init_k<<<(SQ * DIM + 255) / 256, 256>>>();
    // 2. segment ids + masks
    prep_k<<<(NP + 255) / 256, 256>>>(ind);
    // 3. pool branch: mma GEMM + scatter-max
    mma_gemm<1><<<dim3((NP + 127) / 128, 4), 256>>>(feat, Wpool, bpool, nullptr,
                                                    p_pool_key, p_segq, NP);
    // 4. emb branch: mma GEMM + store + scatter-max
    mma_gemm<2><<<dim3((NP + 127) / 128, 4), 256>>>(feat, Wemb, bemb, p_ef,
                                                    p_emb_key, p_segk, NP);
    // 5. per-channel argmax
    argmax_k<<<(NP * DIM) / 256, 256>>>();
    // 6. winner coords
    embc_k<<<SK, 256>>>(ind);
    // 7. PE-added grids
    buildq_k<<<SQ, 256>>>();
    buildkv_k<<<SK, 256>>>();
    // 8. projections (mma)
    mma_gemm<0><<<dim3((SQ + 127) / 128, 4), 256>>>(p_qin, Wq, bq, p_qp, nullptr, nullptr, SQ);
    mma_gemm<0><<<dim3((SK + 127) / 128, 4), 256>>>(p_kv, Wk, bk, p_kb, nullptr, nullptr, SK);
    mma_gemm<0><<<dim3((SK + 127) / 128, 4), 256>>>(p_kv, Wv, bv, p_vb, nullptr, nullptr, SK);
    // 9. attention
    scores_k<<<dim3((GQ + 63) / 64, GK / 64, BATCH * NH), 256>>>(p_qp, p_kb, p_mask_k, p_S);
    softmax_k<<<(BATCH * NH * GQ) / 8, 256>>>(p_S);
    av_k<<<dim3((GQ + 63) / 64, BATCH * NH), 256>>>(p_S, p_vb, p_oa);
    // 10. output projection + residual + LN
    mma_gemm<0><<<dim3((SQ + 127) / 128, 4), 256>>>(p_oa, Wo, bo, p_o2, nullptr, nullptr, SQ);
    ln_k<<<SQ, 256>>>(p_qin, p_o2, lng, lnb, p_mhca);
    // 11. gather + seg head
    head_k<<<NP / 8, 256>>>(feat, Wseg, bseg, out);
}

// round 4
// speedup vs baseline: 1.7090x; 1.3437x over previous
#include <cuda_runtime.h>
#include <cuda_bf16.h>
#include <math.h>
#include <stdint.h>

// ---------------- problem constants ----------------
#define NP   120000
#define DIM  256
#define BATCH 2
#define NH   8
#define NOUT 20
#define ZD 60
#define YD 45
#define XD 4
#define GQ 10800        // ZD*YD*XD
#define SQ 21600        // BATCH*GQ
#define ZE 12
#define YE 24
#define XE 2
#define GK 576          // ZE*YE*XE
#define SK 1152         // BATCH*GK
#define NF 42           // DIM/6
#define PEC 252         // 6*NF

// ---------------- scratch (device globals; no allocation allowed) ----------------
__device__ unsigned g_pool_key[SQ * DIM];
__device__ unsigned g_emb_key[SK * DIM];
__device__ int      g_mask_q[SQ];
__device__ int      g_mask_k[SK];
__device__ int      g_segq[NP];
__device__ int      g_segk[NP];
__device__ float    g_ef[(size_t)NP * DIM];      // 123 MB
__device__ int      g_arg[SK * DIM];
__device__ float    g_embc[SK * 3];
__device__ float    g_qin[(size_t)SQ * DIM];
__device__ float    g_kv[SK * DIM];
__device__ float    g_qp[(size_t)SQ * DIM];
__device__ float    g_kb[SK * DIM];
__device__ float    g_vb[SK * DIM];
__device__ float    g_oa[(size_t)SQ * DIM];
__device__ float    g_o2[(size_t)SQ * DIM];
__device__ float    g_mhca[(size_t)SQ * DIM];
// bf16 hi/lo copies of K/V head slices for flash attention
__device__ __nv_bfloat16 g_k16h[16 * 32 * 576];
__device__ __nv_bfloat16 g_k16l[16 * 32 * 576];
__device__ __nv_bfloat16 g_v16h[16 * 576 * 32];
__device__ __nv_bfloat16 g_v16l[16 * 576 * 32];

// monotonic float<->u32 order-preserving encoding (bijective)
__device__ __forceinline__ unsigned fenc(float f) {
    unsigned u = __float_as_uint(f);
    return (u & 0x80000000u) ? ~u : (u | 0x80000000u);
}
__device__ __forceinline__ float fdec(unsigned k) {
    return __uint_as_float((k & 0x80000000u) ? (k ^ 0x80000000u) : ~k);
}

// ================= warp MMA helpers (baseline sm_80+ features only) =================
__device__ __forceinline__ uint32_t sptr(const void* p) {
    return (uint32_t)__cvta_generic_to_shared(p);
}

#define LDSM_X4(r, addr) \
    asm volatile("ldmatrix.sync.aligned.m8n8.x4.shared.b16 {%0,%1,%2,%3}, [%4];" \
        : "=r"((r)[0]), "=r"((r)[1]), "=r"((r)[2]), "=r"((r)[3]) : "r"(addr))

#define LDSM_X4_T(r, addr) \
    asm volatile("ldmatrix.sync.aligned.m8n8.x4.trans.shared.b16 {%0,%1,%2,%3}, [%4];" \
        : "=r"((r)[0]), "=r"((r)[1]), "=r"((r)[2]), "=r"((r)[3]) : "r"(addr))

__device__ __forceinline__ void mma16816(float* c, const uint32_t* a, uint32_t b0, uint32_t b1) {
    asm volatile(
        "mma.sync.aligned.m16n8k16.row.col.f32.bf16.bf16.f32 "
        "{%0,%1,%2,%3}, {%4,%5,%6,%7}, {%8,%9}, {%0,%1,%2,%3};"
        : "+f"(c[0]), "+f"(c[1]), "+f"(c[2]), "+f"(c[3])
        : "r"(a[0]), "r"(a[1]), "r"(a[2]), "r"(a[3]), "r"(b0), "r"(b1));
}

__device__ __forceinline__ void split_bf16(float v, __nv_bfloat16& h, __nv_bfloat16& l) {
    h = __float2bfloat16(v);
    l = __float2bfloat16(v - __bfloat162float(h));
}

__device__ __forceinline__ void split2pack(float a, float b, uint32_t& hi, uint32_t& lo) {
    __nv_bfloat16 ha = __float2bfloat16(a), hb = __float2bfloat16(b);
    __nv_bfloat16 la = __float2bfloat16(a - __bfloat162float(ha));
    __nv_bfloat16 lb = __float2bfloat16(b - __bfloat162float(hb));
    __nv_bfloat162 th(ha, hb), tl(la, lb);
    hi = *(uint32_t*)&th;
    lo = *(uint32_t*)&tl;
}

// ================= bf16x3 split-precision MMA GEMM ==================
// C[M,256] = A[M,256] @ W[256,256] + bias, computed as Ah*Bh + Ah*Bl + Al*Bh.
// CTA tile 128(m) x 64(n); 256 threads = 8 warps as 2(m) x 4(n), warp tile 64x16.
// MODE 0: store Cout; MODE 1: atomicMax scatter only; MODE 2: store + scatter.
#define APAD 40   // 32 k + 8 pad
#define BPAD 72   // 64 n + 8 pad
template <int MODE>
__global__ __launch_bounds__(256, 2) void mma_gemm(
    const float* __restrict__ A, const float* __restrict__ W,
    const float* __restrict__ bias, float* __restrict__ Cout,
    unsigned* __restrict__ keyOut, const int* __restrict__ segArr, int M)
{
    __shared__ __align__(16) __nv_bfloat16 sA[2][128][APAD];  // [hi/lo][m][k]
    __shared__ __align__(16) __nv_bfloat16 sB[2][32][BPAD];   // [hi/lo][k][n]

    int t = threadIdx.x;
    int wid = t >> 5, lane = t & 31;
    int wm = wid >> 2;
    int wn = wid & 3;
    int m0 = blockIdx.x * 128;
    int c0 = blockIdx.y * 64;

    float acc[4][2][4] = {};

    int a_row = t >> 1;
    int a_cs  = (t & 1) * 16;
    int b_k   = t >> 3;
    int b_ns  = (t & 7) * 8;

    for (int ch = 0; ch < 8; ch++) {
        int k0 = ch * 32;
        {
            bool inb = (m0 + a_row) < M;
            const float* ap = &A[(size_t)(m0 + a_row) * 256 + k0 + a_cs];
#pragma unroll
            for (int q = 0; q < 4; q++) {
                float4 v = inb ? *(const float4*)(ap + q * 4)
                               : make_float4(0.f, 0.f, 0.f, 0.f);
                __nv_bfloat16 hx, lx, hy, ly, hz, lz, hw, lw;
                split_bf16(v.x, hx, lx); split_bf16(v.y, hy, ly);
                split_bf16(v.z, hz, lz); split_bf16(v.w, hw, lw);
                __nv_bfloat162* ph = (__nv_bfloat162*)&sA[0][a_row][a_cs + q * 4];
                ph[0] = __nv_bfloat162(hx, hy);
                ph[1] = __nv_bfloat162(hz, hw);
                __nv_bfloat162* pl = (__nv_bfloat162*)&sA[1][a_row][a_cs + q * 4];
                pl[0] = __nv_bfloat162(lx, ly);
                pl[1] = __nv_bfloat162(lz, lw);
            }
        }
        {
            const float* wp = &W[(size_t)(k0 + b_k) * 256 + c0 + b_ns];
#pragma unroll
            for (int q = 0; q < 2; q++) {
                float4 v = *(const float4*)(wp + q * 4);
                __nv_bfloat16 hx, lx, hy, ly, hz, lz, hw, lw;
                split_bf16(v.x, hx, lx); split_bf16(v.y, hy, ly);
                split_bf16(v.z, hz, lz); split_bf16(v.w, hw, lw);
                __nv_bfloat162* ph = (__nv_bfloat162*)&sB[0][b_k][b_ns + q * 4];
                ph[0] = __nv_bfloat162(hx, hy);
                ph[1] = __nv_bfloat162(hz, hw);
                __nv_bfloat162* pl = (__nv_bfloat162*)&sB[1][b_k][b_ns + q * 4];
                pl[0] = __nv_bfloat162(lx, ly);
                pl[1] = __nv_bfloat162(lz, lw);
            }
        }
        __syncthreads();

#pragma unroll
        for (int ks = 0; ks < 2; ks++) {
            int arow = wm * 64 + (lane & 15);
            int akc = ks * 16 + ((lane & 16) ? 8 : 0);
            int bkr = ks * 16 + (lane & 15);
            int bnc = wn * 16 + ((lane & 16) ? 8 : 0);

            uint32_t af[4][4];
            uint32_t bh[4], bl[4];
#pragma unroll
            for (int mt = 0; mt < 4; mt++)
                LDSM_X4(af[mt], sptr(&sA[0][arow + mt * 16][akc]));
            LDSM_X4_T(bh, sptr(&sB[0][bkr][bnc]));
            LDSM_X4_T(bl, sptr(&sB[1][bkr][bnc]));

#pragma unroll
            for (int mt = 0; mt < 4; mt++) {
#pragma unroll
                for (int nt = 0; nt < 2; nt++) {
                    mma16816(acc[mt][nt], af[mt], bh[nt * 2], bh[nt * 2 + 1]);
                    mma16816(acc[mt][nt], af[mt], bl[nt * 2], bl[nt * 2 + 1]);
                }
            }
#pragma unroll
            for (int mt = 0; mt < 4; mt++)
                LDSM_X4(af[mt], sptr(&sA[1][arow + mt * 16][akc]));
#pragma unroll
            for (int mt = 0; mt < 4; mt++) {
#pragma unroll
                for (int nt = 0; nt < 2; nt++)
                    mma16816(acc[mt][nt], af[mt], bh[nt * 2], bh[nt * 2 + 1]);
            }
        }
        __syncthreads();
    }

    int g = lane >> 2, tid4 = lane & 3;
#pragma unroll
    for (int mt = 0; mt < 4; mt++) {
#pragma unroll
        for (int nt = 0; nt < 2; nt++) {
            int coln = c0 + wn * 16 + nt * 8 + tid4 * 2;
            float b0 = bias[coln], b1 = bias[coln + 1];
#pragma unroll
            for (int half = 0; half < 2; half++) {
                int m = m0 + wm * 64 + mt * 16 + g + half * 8;
                if (m >= M) continue;
                float v0 = acc[mt][nt][half * 2 + 0] + b0;
                float v1 = acc[mt][nt][half * 2 + 1] + b1;
                if (MODE == 0) {
                    Cout[(size_t)m * 256 + coln]     = v0;
                    Cout[(size_t)m * 256 + coln + 1] = v1;
                } else {
                    if (MODE == 2) {
                        Cout[(size_t)m * 256 + coln]     = v0;
                        Cout[(size_t)m * 256 + coln + 1] = v1;
                    }
                    int sg = segArr[m];
                    atomicMax(&keyOut[sg * 256 + coln],     fenc(v0));
                    atomicMax(&keyOut[sg * 256 + coln + 1], fenc(v1));
                }
            }
        }
    }
}

// ---------------- init ----------------
__global__ void init_k() {
    int i = blockIdx.x * 256 + threadIdx.x;
    if (i < SQ * DIM) g_pool_key[i] = 0u;
    if (i < SK * DIM) { g_emb_key[i] = 0u; g_arg[i] = -1; }
    if (i < SQ) g_mask_q[i] = 0;
    if (i < SK) g_mask_k[i] = 0;
}

// ---------------- per-point segment ids + occupancy masks ----------------
__global__ void prep_k(const int* __restrict__ ind) {
    int i = blockIdx.x * 256 + threadIdx.x;
    if (i >= NP) return;
    int b = ind[i * 4 + 0];
    int z = ind[i * 4 + 1];
    int y = ind[i * 4 + 2];
    int x = ind[i * 4 + 3];
    int sq = ((b * ZD + z / 8) * YD + y / 8) * XD + x / 8;
    int sk = ((b * ZE + z / 40) * YE + y / 15) * XE + x / 16;
    g_segq[i] = sq;
    g_segk[i] = sk;
    g_mask_q[sq] = 1;
    g_mask_k[sk] = 1;
}

// ---------------- per-channel argmax (tie -> largest point index) ----------------
__global__ void argmax_k() {
    size_t idx = (size_t)blockIdx.x * 256 + threadIdx.x;
    if (idx >= (size_t)NP * DIM) return;
    int i = (int)(idx >> 8);
    int c = (int)(idx & 255);
    float v = g_ef[idx];
    int s = g_segk[i];
    if (v == fdec(g_emb_key[s * 256 + c])) atomicMax(&g_arg[s * 256 + c], i);
}

// ---------------- emb coords ----------------
__global__ void embc_k(const int* __restrict__ ind) {
    __shared__ float rz[256], ry[256], rx[256];
    int s = blockIdx.x;
    int t = threadIdx.x;
    int idx = g_arg[s * 256 + t];
    int i = idx < 0 ? 0 : idx;
    int z = ind[i * 4 + 1], y = ind[i * 4 + 2], x = ind[i * 4 + 3];
    rz[t] = (float)(z / 40);
    ry[t] = (float)(y / 15);
    rx[t] = (float)(x / 16);
    __syncthreads();
    for (int o = 128; o > 0; o >>= 1) {
        if (t < o) { rz[t] += rz[t + o]; ry[t] += ry[t + o]; rx[t] += rx[t + o]; }
        __syncthreads();
    }
    if (t == 0) {
        g_embc[s * 3 + 0] = rz[0] * (1.f / 256.f) * 40.f;
        g_embc[s * 3 + 1] = ry[0] * (1.f / 256.f) * 15.f;
        g_embc[s * 3 + 2] = rx[0] * (1.f / 256.f) * 16.f;
    }
}

// ---------------- sine positional encoding ----------------
__device__ __forceinline__ float pe_val(float cz, float cy, float cx, int c) {
    if (c >= PEC) return 0.f;
    int axis = c / (2 * NF);
    int r = c - axis * (2 * NF);
    int j = r < NF ? r : r - NF;
    float coord = (axis == 0) ? cz : (axis == 1) ? cy : cx;
    float spd = (axis == 0) ? 480.f : (axis == 1) ? 360.f : 32.f;
    float tpow = powf(10000.f, (float)j * (1.f / (float)NF));
    float ang = coord / spd * 6.283185307179586f / tpow;
    return (r < NF) ? sinf(ang) : cosf(ang);
}

__global__ void buildq_k() {
    int s = blockIdx.x;
    int c = threadIdx.x;
    int rem = s % GQ;
    float cz = (float)((rem / (YD * XD)) * 8);
    float cy = (float)(((rem / XD) % YD) * 8);
    float cx = (float)((rem % XD) * 8);
    float base = g_mask_q[s] ? fdec(g_pool_key[(size_t)s * 256 + c]) : 0.f;
    g_qin[(size_t)s * 256 + c] = base + pe_val(cz, cy, cx, c);
}

__global__ void buildkv_k() {
    int s = blockIdx.x;
    int c = threadIdx.x;
    float cz = g_embc[s * 3 + 0];
    float cy = g_embc[s * 3 + 1];
    float cx = g_embc[s * 3 + 2];
    float base = g_mask_k[s] ? fdec(g_emb_key[s * 256 + c]) : 0.f;
    g_kv[s * 256 + c] = base + pe_val(cz, cy, cx, c);
}

// ---------------- convert K/V head slices to bf16 hi/lo ----------------
__global__ void convkv_k() {
    int bh = blockIdx.x;
    int b = bh >> 3, h = bh & 7;
    for (int idx = threadIdx.x; idx < 576 * 32; idx += blockDim.x) {
        int d = idx / 576, key = idx - d * 576;
        float v = g_kb[(size_t)(b * GK + key) * 256 + h * 32 + d];
        __nv_bfloat16 hi, lo;
        split_bf16(v, hi, lo);
        g_k16h[(bh * 32 + d) * 576 + key] = hi;
        g_k16l[(bh * 32 + d) * 576 + key] = lo;
        int key2 = idx >> 5, d2 = idx & 31;
        float w = g_vb[(size_t)(b * GK + key2) * 256 + h * 32 + d2];
        split_bf16(w, hi, lo);
        g_v16h[(bh * 576 + key2) * 32 + d2] = hi;
        g_v16l[(bh * 576 + key2) * 32 + d2] = lo;
    }
}

// ---------------- fused flash attention: scores + softmax + AV ----------------
// Block: 128 threads (4 warps). Each warp: 16 q rows, online softmax over 9
// chunks of 64 keys. Scores and AV via mma bf16x3 split precision.
__global__ __launch_bounds__(128) void fattn_k(const float* __restrict__ qp,
                                               const int* __restrict__ maskk,
                                               float* __restrict__ oa) {
    __shared__ __align__(16) __nv_bfloat16 sQ[2][64][APAD];   // [hi/lo][q][d]
    __shared__ __align__(16) __nv_bfloat16 sK[2][32][BPAD];   // [hi/lo][d][key64]
    __shared__ __align__(16) __nv_bfloat16 sV[2][64][APAD];   // [hi/lo][key][d]
    __shared__ int smask[GK];

    int t = threadIdx.x, wid = t >> 5, lane = t & 31;
    int bh = blockIdx.y, b = bh >> 3, h = bh & 7;
    int q0 = blockIdx.x * 64;
    const float scale = 0.17677669529663687f;   // 1/sqrt(32)

    // ---- load Q tile (scaled), split ----
    {
        int row = t >> 1, cs = (t & 1) * 16;
        bool inb = (q0 + row) < GQ;
        const float* qpp = &qp[(size_t)(b * GQ + q0 + row) * 256 + h * 32 + cs];
#pragma unroll
        for (int q = 0; q < 4; q++) {
            float4 v = inb ? *(const float4*)(qpp + q * 4) : make_float4(0.f, 0.f, 0.f, 0.f);
            v.x *= scale; v.y *= scale; v.z *= scale; v.w *= scale;
            __nv_bfloat16 hx, lx, hy, ly, hz, lz, hw, lw;
            split_bf16(v.x, hx, lx); split_bf16(v.y, hy, ly);
            split_bf16(v.z, hz, lz); split_bf16(v.w, hw, lw);
            __nv_bfloat162* ph = (__nv_bfloat162*)&sQ[0][row][cs + q * 4];
            ph[0] = __nv_bfloat162(hx, hy);
            ph[1] = __nv_bfloat162(hz, hw);
            __nv_bfloat162* pl = (__nv_bfloat162*)&sQ[1][row][cs + q * 4];
            pl[0] = __nv_bfloat162(lx, ly);
            pl[1] = __nv_bfloat162(lz, lw);
        }
    }
    for (int i = t; i < GK; i += 128) smask[i] = maskk[b * GK + i];
    __syncthreads();

    // ---- Q fragments (kept in registers for whole kernel) ----
    uint32_t qh[2][4], ql[2][4];
    {
        int arow = wid * 16 + (lane & 15);
#pragma unroll
        for (int s = 0; s < 2; s++) {
            int akc = s * 16 + ((lane & 16) ? 8 : 0);
            LDSM_X4(qh[s], sptr(&sQ[0][arow][akc]));
            LDSM_X4(ql[s], sptr(&sQ[1][arow][akc]));
        }
    }

    float m0r = -INFINITY, m1r = -INFINITY, l0 = 0.f, l1 = 0.f;
    float oacc[4][4] = {};
    int g = lane >> 2, tid4 = lane & 3;
    int bkr = lane & 15;
    int bsel = (lane & 16) ? 8 : 0;

    for (int c = 0; c < 9; c++) {
        // ---- stage K chunk [32 d][64 keys] ----
        {
            int d = t >> 2, ks = (t & 3) * 16;
            size_t src = (size_t)(bh * 32 + d) * 576 + c * 64 + ks;
            const uint4* sh = (const uint4*)&g_k16h[src];
            const uint4* sl = (const uint4*)&g_k16l[src];
            uint4* dh = (uint4*)&sK[0][d][ks];
            uint4* dl = (uint4*)&sK[1][d][ks];
            dh[0] = sh[0]; dh[1] = sh[1];
            dl[0] = sl[0]; dl[1] = sl[1];
        }
        // ---- stage V chunk [64 keys][32 d] ----
        {
            int key = t >> 1, ds = (t & 1) * 16;
            size_t src = (size_t)(bh * 576 + c * 64 + key) * 32 + ds;
            const uint4* sh = (const uint4*)&g_v16h[src];
            const uint4* sl = (const uint4*)&g_v16l[src];
            uint4* dh = (uint4*)&sV[0][key][ds];
            uint4* dl = (uint4*)&sV[1][key][ds];
            dh[0] = sh[0]; dh[1] = sh[1];
            dl[0] = sl[0]; dl[1] = sl[1];
        }
        __syncthreads();

        // ---- scores: acc[8 n8-tiles][4] = Q (16x32) . K^T (32x64) ----
        float acc[8][4] = {};
#pragma unroll
        for (int s = 0; s < 2; s++) {
#pragma unroll
            for (int j = 0; j < 4; j++) {
                uint32_t kh_[4], kl_[4];
                LDSM_X4_T(kh_, sptr(&sK[0][s * 16 + bkr][j * 16 + bsel]));
                LDSM_X4_T(kl_, sptr(&sK[1][s * 16 + bkr][j * 16 + bsel]));
                mma16816(acc[2 * j],     qh[s], kh_[0], kh_[1]);
                mma16816(acc[2 * j],     qh[s], kl_[0], kl_[1]);
                mma16816(acc[2 * j],     ql[s], kh_[0], kh_[1]);
                mma16816(acc[2 * j + 1], qh[s], kh_[2], kh_[3]);
                mma16816(acc[2 * j + 1], qh[s], kl_[2], kl_[3]);
                mma16816(acc[2 * j + 1], ql[s], kh_[2], kh_[3]);
            }
        }
        // ---- mask (replace with -1e9 like reference) ----
#pragma unroll
        for (int j = 0; j < 8; j++) {
            int key = c * 64 + j * 8 + tid4 * 2;
            if (!smask[key])     { acc[j][0] = -1e9f; acc[j][2] = -1e9f; }
            if (!smask[key + 1]) { acc[j][1] = -1e9f; acc[j][3] = -1e9f; }
        }
        // ---- online softmax update ----
        float mx0 = -INFINITY, mx1 = -INFINITY;
#pragma unroll
        for (int j = 0; j < 8; j++) {
            mx0 = fmaxf(mx0, fmaxf(acc[j][0], acc[j][1]));
            mx1 = fmaxf(mx1, fmaxf(acc[j][2], acc[j][3]));
        }
        mx0 = fmaxf(mx0, __shfl_xor_sync(0xFFFFFFFFu, mx0, 1));
        mx0 = fmaxf(mx0, __shfl_xor_sync(0xFFFFFFFFu, mx0, 2));
        mx1 = fmaxf(mx1, __shfl_xor_sync(0xFFFFFFFFu, mx1, 1));
        mx1 = fmaxf(mx1, __shfl_xor_sync(0xFFFFFFFFu, mx1, 2));
        float mn0 = fmaxf(m0r, mx0), mn1 = fmaxf(m1r, mx1);
        float rs0 = __expf(m0r - mn0), rs1 = __expf(m1r - mn1);
        float sum0 = 0.f, sum1 = 0.f;
#pragma unroll
        for (int j = 0; j < 8; j++) {
            acc[j][0] = __expf(acc[j][0] - mn0);
            acc[j][1] = __expf(acc[j][1] - mn0);
            acc[j][2] = __expf(acc[j][2] - mn1);
            acc[j][3] = __expf(acc[j][3] - mn1);
            sum0 += acc[j][0] + acc[j][1];
            sum1 += acc[j][2] + acc[j][3];
        }
        sum0 += __shfl_xor_sync(0xFFFFFFFFu, sum0, 1);
        sum0 += __shfl_xor_sync(0xFFFFFFFFu, sum0, 2);
        sum1 += __shfl_xor_sync(0xFFFFFFFFu, sum1, 1);
        sum1 += __shfl_xor_sync(0xFFFFFFFFu, sum1, 2);
        l0 = l0 * rs0 + sum0;
        l1 = l1 * rs1 + sum1;
#pragma unroll
        for (int dt = 0; dt < 4; dt++) {
            oacc[dt][0] *= rs0; oacc[dt][1] *= rs0;
            oacc[dt][2] *= rs1; oacc[dt][3] *= rs1;
        }
        m0r = mn0; m1r = mn1;

        // ---- AV: oacc += P (16x64) . V (64x32), P from registers ----
#pragma unroll
        for (int kt = 0; kt < 4; kt++) {
            uint32_t pha[4], pla[4];
            split2pack(acc[2 * kt][0],     acc[2 * kt][1],     pha[0], pla[0]);
            split2pack(acc[2 * kt][2],     acc[2 * kt][3],     pha[1], pla[1]);
            split2pack(acc[2 * kt + 1][0], acc[2 * kt + 1][1], pha[2], pla[2]);
            split2pack(acc[2 * kt + 1][2], acc[2 * kt + 1][3], pha[3], pla[3]);
#pragma unroll
            for (int dh2 = 0; dh2 < 2; dh2++) {
                uint32_t vh_[4], vl_[4];
                LDSM_X4_T(vh_, sptr(&sV[0][kt * 16 + bkr][dh2 * 16 + bsel]));
                LDSM_X4_T(vl_, sptr(&sV[1][kt * 16 + bkr][dh2 * 16 + bsel]));
                mma16816(oacc[dh2 * 2],     pha, vh_[0], vh_[1]);
                mma16816(oacc[dh2 * 2],     pha, vl_[0], vl_[1]);
                mma16816(oacc[dh2 * 2],     pla, vh_[0], vh_[1]);
                mma16816(oacc[dh2 * 2 + 1], pha, vh_[2], vh_[3]);
                mma16816(oacc[dh2 * 2 + 1], pha, vl_[2], vl_[3]);
                mma16816(oacc[dh2 * 2 + 1], pla, vh_[2], vh_[3]);
            }
        }
        __syncthreads();
    }

    // ---- finalize + store ----
    float inv0 = 1.f / l0, inv1 = 1.f / l1;
    int qa = q0 + wid * 16 + g;
    int qb = qa + 8;
#pragma unroll
    for (int dt = 0; dt < 4; dt++) {
        int dim = h * 32 + dt * 8 + tid4 * 2;
        if (qa < GQ) {
            oa[(size_t)(b * GQ + qa) * 256 + dim]     = oacc[dt][0] * inv0;
            oa[(size_t)(b * GQ + qa) * 256 + dim + 1] = oacc[dt][1] * inv0;
        }
        if (qb < GQ) {
            oa[(size_t)(b * GQ + qb) * 256 + dim]     = oacc[dt][2] * inv1;
            oa[(size_t)(b * GQ + qb) * 256 + dim + 1] = oacc[dt][3] * inv1;
        }
    }
}

// ---------------- residual + LayerNorm ----------------
__global__ void ln_k(const float* __restrict__ qin, const float* __restrict__ o2,
                     const float* __restrict__ g, const float* __restrict__ bb,
                     float* __restrict__ out) {
    __shared__ float red[256];
    __shared__ float mu_s, var_s;
    int r = blockIdx.x;
    int c = threadIdx.x;
    float h = qin[(size_t)r * 256 + c] + o2[(size_t)r * 256 + c];
    red[c] = h;
    __syncthreads();
    for (int o = 128; o > 0; o >>= 1) {
        if (c < o) red[c] += red[c + o];
        __syncthreads();
    }
    if (c == 0) mu_s = red[0] * (1.f / 256.f);
    __syncthreads();
    float d = h - mu_s;
    red[c] = d * d;
    __syncthreads();
    for (int o = 128; o > 0; o >>= 1) {
        if (c < o) red[c] += red[c + o];
        __syncthreads();
    }
    if (c == 0) var_s = red[0] * (1.f / 256.f);
    __syncthreads();
    out[(size_t)r * 256 + c] = d * rsqrtf(var_s + 1e-5f) * g[c] + bb[c];
}

// ---------------- final gather + seg head ----------------
__global__ void head_k(const float* __restrict__ feat, const float* __restrict__ Wseg,
                       const float* __restrict__ bseg, float* __restrict__ out) {
    __shared__ float Ws[256 * NOUT];
    int t = threadIdx.x;
    for (int i = t; i < 256 * NOUT; i += 256) Ws[i] = Wseg[i];
    __syncthreads();
    int p = blockIdx.x * 8 + (t >> 5);
    int lane = t & 31;
    int sg = g_segq[p];
    float v[8];
#pragma unroll
    for (int r = 0; r < 8; r++) {
        int c = lane + 32 * r;
        v[r] = feat[(size_t)p * 256 + c] + g_mhca[(size_t)sg * 256 + c];
    }
#pragma unroll
    for (int j = 0; j < NOUT; j++) {
        float s = 0.f;
#pragma unroll
        for (int r = 0; r < 8; r++) s = fmaf(v[r], Ws[(lane + 32 * r) * NOUT + j], s);
#pragma unroll
        for (int o = 16; o; o >>= 1) s += __shfl_xor_sync(0xFFFFFFFFu, s, o);
        if (lane == 0) out[(size_t)p * NOUT + j] = s + bseg[j];
    }
}

// ---------------- host launch ----------------
static void* sym_addr(const void* symbol) {
    void* p = nullptr;
    cudaGetSymbolAddress(&p, symbol);
    return p;
}

extern "C" void kernel_launch(void* const* d_in, const int* in_sizes, int n_in,
                              void* d_out, int out_size) {
    const float* feat  = (const float*)d_in[0];
    const float* Wpool = (const float*)d_in[1];
    const float* bpool = (const float*)d_in[2];
    const float* Wemb  = (const float*)d_in[3];
    const float* bemb  = (const float*)d_in[4];
    const float* Wq    = (const float*)d_in[5];
    const float* bq    = (const float*)d_in[6];
    const float* Wk    = (const float*)d_in[7];
    const float* bk    = (const float*)d_in[8];
    const float* Wv    = (const float*)d_in[9];
    const float* bv    = (const float*)d_in[10];
    const float* Wo    = (const float*)d_in[11];
    const float* bo    = (const float*)d_in[12];
    const float* lng   = (const float*)d_in[13];
    const float* lnb   = (const float*)d_in[14];
    const float* Wseg  = (const float*)d_in[15];
    const float* bseg  = (const float*)d_in[16];
    const int*   ind   = (const int*)d_in[17];
    float* out = (float*)d_out;

    unsigned* p_pool_key = (unsigned*)sym_addr(g_pool_key);
    unsigned* p_emb_key  = (unsigned*)sym_addr(g_emb_key);
    int*      p_segq     = (int*)sym_addr(g_segq);
    int*      p_segk     = (int*)sym_addr(g_segk);
    int*      p_mask_k   = (int*)sym_addr(g_mask_k);
    float*    p_ef       = (float*)sym_addr(g_ef);
    float*    p_qin      = (float*)sym_addr(g_qin);
    float*    p_kv       = (float*)sym_addr(g_kv);
    float*    p_qp       = (float*)sym_addr(g_qp);
    float*    p_kb       = (float*)sym_addr(g_kb);
    float*    p_vb       = (float*)sym_addr(g_vb);
    float*    p_oa       = (float*)sym_addr(g_oa);
    float*    p_o2       = (float*)sym_addr(g_o2);
    float*    p_mhca     = (float*)sym_addr(g_mhca);

    // 1. init scratch
    init_k<<<(SQ * DIM + 255) / 256, 256>>>();
    // 2. segment ids + masks
    prep_k<<<(NP + 255) / 256, 256>>>(ind);
    // 3. pool branch: mma GEMM + scatter-max
    mma_gemm<1><<<dim3((NP + 127) / 128, 4), 256>>>(feat, Wpool, bpool, nullptr,
                                                    p_pool_key, p_segq, NP);
    // 4. emb branch: mma GEMM + store + scatter-max
    mma_gemm<2><<<dim3((NP + 127) / 128, 4), 256>>>(feat, Wemb, bemb, p_ef,
                                                    p_emb_key, p_segk, NP);
    // 5. per-channel argmax
    argmax_k<<<(NP * DIM) / 256, 256>>>();
    // 6. winner coords
    embc_k<<<SK, 256>>>(ind);
    // 7. PE-added grids
    buildq_k<<<SQ, 256>>>();
    buildkv_k<<<SK, 256>>>();
    // 8. projections (mma)
    mma_gemm<0><<<dim3((SQ + 127) / 128, 4), 256>>>(p_qin, Wq, bq, p_qp, nullptr, nullptr, SQ);
    mma_gemm<0><<<dim3((SK + 127) / 128, 4), 256>>>(p_kv, Wk, bk, p_kb, nullptr, nullptr, SK);
    mma_gemm<0><<<dim3((SK + 127) / 128, 4), 256>>>(p_kv, Wv, bv, p_vb, nullptr, nullptr, SK);
    // 9. fused flash attention
    convkv_k<<<16, 256>>>();
    fattn_k<<<dim3((GQ + 63) / 64, BATCH * NH), 128>>>(p_qp, p_mask_k, p_oa);
    // 10. output projection + residual + LN
    mma_gemm<0><<<dim3((SQ + 127) / 128, 4), 256>>>(p_oa, Wo, bo, p_o2, nullptr, nullptr, SQ);
    ln_k<<<SQ, 256>>>(p_qin, p_o2, lng, lnb, p_mhca);
    // 11. gather + seg head
    head_k<<<NP / 8, 256>>>(feat, Wseg, bseg, out);
}

// round 5
// speedup vs baseline: 1.9631x; 1.1487x over previous
#include <cuda_runtime.h>
#include <cuda_bf16.h>
#include <math.h>
#include <stdint.h>

// ---------------- problem constants ----------------
#define NP   120000
#define DIM  256
#define BATCH 2
#define NH   8
#define NOUT 20
#define ZD 60
#define YD 45
#define XD 4
#define GQ 10800        // ZD*YD*XD
#define SQ 21600        // BATCH*GQ
#define ZE 12
#define YE 24
#define XE 2
#define GK 576          // ZE*YE*XE
#define SK 1152         // BATCH*GK
#define NF 42           // DIM/6
#define PEC 252         // 6*NF

// ---------------- scratch (device globals; no allocation allowed) ----------------
__device__ unsigned g_pool_key[SQ * DIM];
__device__ unsigned g_emb_key[SK * DIM];
__device__ int      g_mask_q[SQ];
__device__ int      g_mask_k[SK];
__device__ int      g_segq[NP];
__device__ int      g_segk[NP];
__device__ float    g_ef[(size_t)NP * DIM];      // 123 MB
__device__ int      g_arg[SK * DIM];
__device__ float    g_embc[SK * 3];
__device__ float    g_qin[(size_t)SQ * DIM];
__device__ float    g_o2[(size_t)SQ * DIM];
__device__ float    g_mhca[(size_t)SQ * DIM];
// bf16 hi/lo split buffers
__device__ __nv_bfloat16 g_featH[(size_t)NP * DIM];
__device__ __nv_bfloat16 g_featL[(size_t)NP * DIM];
__device__ __nv_bfloat16 g_wH[6 * 65536];
__device__ __nv_bfloat16 g_wL[6 * 65536];
__device__ __nv_bfloat16 g_qinH[(size_t)SQ * DIM];
__device__ __nv_bfloat16 g_qinL[(size_t)SQ * DIM];
__device__ __nv_bfloat16 g_kvH[SK * DIM];
__device__ __nv_bfloat16 g_kvL[SK * DIM];
__device__ __nv_bfloat16 g_qpH[(size_t)SQ * DIM];
__device__ __nv_bfloat16 g_qpL[(size_t)SQ * DIM];
__device__ __nv_bfloat16 g_oaH[(size_t)SQ * DIM];
__device__ __nv_bfloat16 g_oaL[(size_t)SQ * DIM];
__device__ __nv_bfloat16 g_k16h[16 * 32 * 576];
__device__ __nv_bfloat16 g_k16l[16 * 32 * 576];
__device__ __nv_bfloat16 g_v16h[16 * 576 * 32];
__device__ __nv_bfloat16 g_v16l[16 * 576 * 32];

// monotonic float<->u32 order-preserving encoding (bijective)
__device__ __forceinline__ unsigned fenc(float f) {
    unsigned u = __float_as_uint(f);
    return (u & 0x80000000u) ? ~u : (u | 0x80000000u);
}
__device__ __forceinline__ float fdec(unsigned k) {
    return __uint_as_float((k & 0x80000000u) ? (k ^ 0x80000000u) : ~k);
}

// ================= warp MMA helpers (baseline sm_80+ features only) =================
__device__ __forceinline__ uint32_t sptr(const void* p) {
    return (uint32_t)__cvta_generic_to_shared(p);
}

#define LDSM_X4(r, addr) \
    asm volatile("ldmatrix.sync.aligned.m8n8.x4.shared.b16 {%0,%1,%2,%3}, [%4];" \
        : "=r"((r)[0]), "=r"((r)[1]), "=r"((r)[2]), "=r"((r)[3]) : "r"(addr))

#define LDSM_X4_T(r, addr) \
    asm volatile("ldmatrix.sync.aligned.m8n8.x4.trans.shared.b16 {%0,%1,%2,%3}, [%4];" \
        : "=r"((r)[0]), "=r"((r)[1]), "=r"((r)[2]), "=r"((r)[3]) : "r"(addr))

__device__ __forceinline__ void mma16816(float* c, const uint32_t* a, uint32_t b0, uint32_t b1) {
    asm volatile(
        "mma.sync.aligned.m16n8k16.row.col.f32.bf16.bf16.f32 "
        "{%0,%1,%2,%3}, {%4,%5,%6,%7}, {%8,%9}, {%0,%1,%2,%3};"
        : "+f"(c[0]), "+f"(c[1]), "+f"(c[2]), "+f"(c[3])
        : "r"(a[0]), "r"(a[1]), "r"(a[2]), "r"(a[3]), "r"(b0), "r"(b1));
}

#define CP16(dst, src) \
    asm volatile("cp.async.cg.shared.global [%0], [%1], 16;\n" :: "r"(dst), "l"(src))
#define CP_COMMIT asm volatile("cp.async.commit_group;\n" ::: "memory")
#define CP_WAIT1 asm volatile("cp.async.wait_group 1;\n" ::: "memory")
#define CP_WAIT0 asm volatile("cp.async.wait_group 0;\n" ::: "memory")

__device__ __forceinline__ void split_bf16(float v, __nv_bfloat16& h, __nv_bfloat16& l) {
    h = __float2bfloat16(v);
    l = __float2bfloat16(v - __bfloat162float(h));
}

__device__ __forceinline__ void split2pack(float a, float b, uint32_t& hi, uint32_t& lo) {
    __nv_bfloat16 ha = __float2bfloat16(a), hb = __float2bfloat16(b);
    __nv_bfloat16 la = __float2bfloat16(a - __bfloat162float(ha));
    __nv_bfloat16 lb = __float2bfloat16(b - __bfloat162float(hb));
    __nv_bfloat162 th(ha, hb), tl(la, lb);
    hi = *(uint32_t*)&th;
    lo = *(uint32_t*)&tl;
}

// ---------------- split kernels ----------------
__global__ void split_feat_k(const float* __restrict__ src) {
    size_t i = (size_t)blockIdx.x * 256 + threadIdx.x;  // per 4 elements
    if (i * 4 >= (size_t)NP * DIM) return;
    float4 v = ((const float4*)src)[i];
    __nv_bfloat16 hx, lx, hy, ly, hz, lz, hw, lw;
    split_bf16(v.x, hx, lx); split_bf16(v.y, hy, ly);
    split_bf16(v.z, hz, lz); split_bf16(v.w, hw, lw);
    ((__nv_bfloat162*)g_featH)[i * 2]     = __nv_bfloat162(hx, hy);
    ((__nv_bfloat162*)g_featH)[i * 2 + 1] = __nv_bfloat162(hz, hw);
    ((__nv_bfloat162*)g_featL)[i * 2]     = __nv_bfloat162(lx, ly);
    ((__nv_bfloat162*)g_featL)[i * 2 + 1] = __nv_bfloat162(lz, lw);
}

__global__ void split_w_k(const float* __restrict__ w0, const float* __restrict__ w1,
                          const float* __restrict__ w2, const float* __restrict__ w3,
                          const float* __restrict__ w4, const float* __restrict__ w5) {
    int i = blockIdx.x * 256 + threadIdx.x;       // per 4 elements, 6*16384 total
    if (i >= 6 * 16384) return;
    int which = i >> 14;
    int off = i & 16383;
    const float* src = which == 0 ? w0 : which == 1 ? w1 : which == 2 ? w2
                     : which == 3 ? w3 : which == 4 ? w4 : w5;
    float4 v = ((const float4*)src)[off];
    __nv_bfloat16 hx, lx, hy, ly, hz, lz, hw, lw;
    split_bf16(v.x, hx, lx); split_bf16(v.y, hy, ly);
    split_bf16(v.z, hz, lz); split_bf16(v.w, hw, lw);
    ((__nv_bfloat162*)g_wH)[i * 2]     = __nv_bfloat162(hx, hy);
    ((__nv_bfloat162*)g_wH)[i * 2 + 1] = __nv_bfloat162(hz, hw);
    ((__nv_bfloat162*)g_wL)[i * 2]     = __nv_bfloat162(lx, ly);
    ((__nv_bfloat162*)g_wL)[i * 2 + 1] = __nv_bfloat162(lz, lw);
}

// ================= pipelined bf16x3 MMA GEMM =====================
// C[M,256] = A[M,256] @ W[256,256] + bias; A,W pre-split bf16 hi/lo.
// CTA tile 128m x 64n; 8 warps 2x4; cp.async 2-stage pipeline; K chunk 32.
// Grid: (cblocks, mblocks) — column block in x for L2 reuse of A.
// MODE 10: fused pool(emb) — gridDim.x=8: cblk<4 pool scatter, else ef store+emb scatter
// MODE 0:  store fp32 Cout
// MODE 3:  store split bf16 (v*scale) to outH/outL
// MODE 4:  K-proj: split store to [bh][d][key] layout
// MODE 5:  V-proj: split store to [bh][key][d] layout
#define SA_BYTES (2 * 2 * 128 * 40 * 2)
#define SB_BYTES (2 * 2 * 32 * 72 * 2)
#define GEMM_SMEM (SA_BYTES + SB_BYTES)

__device__ __forceinline__ __nv_bfloat16* pA(__nv_bfloat16* b, int st, int mat, int r) {
    return b + ((size_t)((st * 2 + mat) * 128 + r)) * 40;
}
__device__ __forceinline__ __nv_bfloat16* pB(__nv_bfloat16* b, int st, int mat, int r) {
    return b + ((size_t)((st * 2 + mat) * 32 + r)) * 72;
}

template <int MODE>
__global__ __launch_bounds__(256, 2) void bf_gemm(
    const __nv_bfloat16* __restrict__ Ah, const __nv_bfloat16* __restrict__ Al,
    const __nv_bfloat16* __restrict__ WhA, const __nv_bfloat16* __restrict__ WlA,
    const float* __restrict__ biasA,
    const __nv_bfloat16* __restrict__ WhB, const __nv_bfloat16* __restrict__ WlB,
    const float* __restrict__ biasB,
    float* __restrict__ Cout,
    unsigned* __restrict__ keyP, const int* __restrict__ segP,
    unsigned* __restrict__ keyE, const int* __restrict__ segE,
    __nv_bfloat16* __restrict__ outH, __nv_bfloat16* __restrict__ outL,
    float scale, int M)
{
    extern __shared__ char dsm[];
    __nv_bfloat16* sA = (__nv_bfloat16*)dsm;
    __nv_bfloat16* sB = (__nv_bfloat16*)(dsm + SA_BYTES);

    int t = threadIdx.x, wid = t >> 5, lane = t & 31;
    int wm = wid >> 2, wn = wid & 3;
    int m0 = blockIdx.y * 128;
    int cblk = blockIdx.x;

    const __nv_bfloat16 *Whp, *Wlp;
    const float* bp;
    int c0;
    bool isPool = false;
    if (MODE == 10) {
        isPool = cblk < 4;
        Whp = isPool ? WhA : WhB;
        Wlp = isPool ? WlA : WlB;
        bp  = isPool ? biasA : biasB;
        c0 = (cblk & 3) * 64;
    } else {
        Whp = WhA; Wlp = WlA; bp = biasA;
        c0 = cblk * 64;
    }

    float acc[4][2][4] = {};

    auto copyA = [&](int st, int ch) {
        int k0 = ch * 32;
#pragma unroll
        for (int i = 0; i < 2; i++) {
            int op = t * 2 + i;
            int r = op >> 2, seg = op & 3;
            int rowc = m0 + r;
            if (rowc >= M) rowc = M - 1;
            size_t src = (size_t)rowc * 256 + k0 + seg * 8;
            CP16(sptr(pA(sA, st, 0, r) + seg * 8), Ah + src);
            CP16(sptr(pA(sA, st, 1, r) + seg * 8), Al + src);
        }
    };
    auto copyB = [&](int st, int ch) {
        int k0 = ch * 32;
        int r = t >> 3, seg = t & 7;
        size_t src = (size_t)(k0 + r) * 256 + c0 + seg * 8;
        CP16(sptr(pB(sB, st, 0, r) + seg * 8), Whp + src);
        CP16(sptr(pB(sB, st, 1, r) + seg * 8), Wlp + src);
    };

    copyA(0, 0);
    copyB(0, 0);
    CP_COMMIT;

    for (int ch = 0; ch < 8; ch++) {
        if (ch < 7) {
            copyA((ch + 1) & 1, ch + 1);
            copyB((ch + 1) & 1, ch + 1);
            CP_COMMIT;
            CP_WAIT1;
        } else {
            CP_WAIT0;
        }
        __syncthreads();
        int st = ch & 1;
#pragma unroll
        for (int ks = 0; ks < 2; ks++) {
            int arow = wm * 64 + (lane & 15);
            int akc = ks * 16 + ((lane & 16) ? 8 : 0);
            int bkr = ks * 16 + (lane & 15);
            int bnc = wn * 16 + ((lane & 16) ? 8 : 0);

            uint32_t af[4][4], bh[4], bl[4];
#pragma unroll
            for (int mt = 0; mt < 4; mt++)
                LDSM_X4(af[mt], sptr(pA(sA, st, 0, arow + mt * 16) + akc));
            LDSM_X4_T(bh, sptr(pB(sB, st, 0, bkr) + bnc));
            LDSM_X4_T(bl, sptr(pB(sB, st, 1, bkr) + bnc));

#pragma unroll
            for (int mt = 0; mt < 4; mt++) {
#pragma unroll
                for (int nt = 0; nt < 2; nt++) {
                    mma16816(acc[mt][nt], af[mt], bh[nt * 2], bh[nt * 2 + 1]);
                    mma16816(acc[mt][nt], af[mt], bl[nt * 2], bl[nt * 2 + 1]);
                }
            }
#pragma unroll
            for (int mt = 0; mt < 4; mt++)
                LDSM_X4(af[mt], sptr(pA(sA, st, 1, arow + mt * 16) + akc));
#pragma unroll
            for (int mt = 0; mt < 4; mt++) {
#pragma unroll
                for (int nt = 0; nt < 2; nt++)
                    mma16816(acc[mt][nt], af[mt], bh[nt * 2], bh[nt * 2 + 1]);
            }
        }
        __syncthreads();
    }

    // ---- epilogue ----
    int g = lane >> 2, tid4 = lane & 3;
#pragma unroll
    for (int mt = 0; mt < 4; mt++) {
#pragma unroll
        for (int nt = 0; nt < 2; nt++) {
            int coln = c0 + wn * 16 + nt * 8 + tid4 * 2;
            float b0 = bp[coln], b1 = bp[coln + 1];
#pragma unroll
            for (int half = 0; half < 2; half++) {
                int m = m0 + wm * 64 + mt * 16 + g + half * 8;
                if (m >= M) continue;
                float v0 = acc[mt][nt][half * 2 + 0] + b0;
                float v1 = acc[mt][nt][half * 2 + 1] + b1;
                if (MODE == 0) {
                    Cout[(size_t)m * 256 + coln]     = v0;
                    Cout[(size_t)m * 256 + coln + 1] = v1;
                } else if (MODE == 10) {
                    if (isPool) {
                        int sg = segP[m];
                        atomicMax(&keyP[sg * 256 + coln],     fenc(v0));
                        atomicMax(&keyP[sg * 256 + coln + 1], fenc(v1));
                    } else {
                        Cout[(size_t)m * 256 + coln]     = v0;
                        Cout[(size_t)m * 256 + coln + 1] = v1;
                        int sg = segE[m];
                        atomicMax(&keyE[sg * 256 + coln],     fenc(v0));
                        atomicMax(&keyE[sg * 256 + coln + 1], fenc(v1));
                    }
                } else if (MODE == 3) {
                    uint32_t hi, lo;
                    split2pack(v0 * scale, v1 * scale, hi, lo);
                    *(uint32_t*)&outH[(size_t)m * 256 + coln] = hi;
                    *(uint32_t*)&outL[(size_t)m * 256 + coln] = lo;
                } else if (MODE == 4) {
                    int b_ = m / 576, key = m - b_ * 576;
                    int hh = coln >> 5, d = coln & 31;
                    __nv_bfloat16 H, L;
                    split_bf16(v0, H, L);
                    size_t dst0 = (size_t)((b_ * 8 + hh) * 32 + d) * 576 + key;
                    outH[dst0] = H; outL[dst0] = L;
                    split_bf16(v1, H, L);
                    size_t dst1 = dst0 + 576;
                    outH[dst1] = H; outL[dst1] = L;
                } else if (MODE == 5) {
                    int b_ = m / 576, key = m - b_ * 576;
                    int hh = coln >> 5, d = coln & 31;
                    __nv_bfloat16 H, L;
                    size_t dst0 = ((size_t)(b_ * 8 + hh) * 576 + key) * 32 + d;
                    split_bf16(v0, H, L);
                    outH[dst0] = H; outL[dst0] = L;
                    split_bf16(v1, H, L);
                    outH[dst0 + 1] = H; outL[dst0 + 1] = L;
                }
            }
        }
    }
}

// ---------------- init ----------------
__global__ void init_k() {
    int i = blockIdx.x * 256 + threadIdx.x;
    if (i < SQ * DIM) g_pool_key[i] = 0u;
    if (i < SK * DIM) { g_emb_key[i] = 0u; g_arg[i] = -1; }
    if (i < SQ) g_mask_q[i] = 0;
    if (i < SK) g_mask_k[i] = 0;
}

// ---------------- per-point segment ids + occupancy masks ----------------
__global__ void prep_k(const int* __restrict__ ind) {
    int i = blockIdx.x * 256 + threadIdx.x;
    if (i >= NP) return;
    int b = ind[i * 4 + 0];
    int z = ind[i * 4 + 1];
    int y = ind[i * 4 + 2];
    int x = ind[i * 4 + 3];
    int sq = ((b * ZD + z / 8) * YD + y / 8) * XD + x / 8;
    int sk = ((b * ZE + z / 40) * YE + y / 15) * XE + x / 16;
    g_segq[i] = sq;
    g_segk[i] = sk;
    g_mask_q[sq] = 1;
    g_mask_k[sk] = 1;
}

// ---------------- per-channel argmax (tie -> largest point index) ----------------
__global__ void argmax_k() {
    size_t idx = (size_t)blockIdx.x * 256 + threadIdx.x;
    if (idx >= (size_t)NP * DIM) return;
    int i = (int)(idx >> 8);
    int c = (int)(idx & 255);
    float v = g_ef[idx];
    int s = g_segk[i];
    if (v == fdec(g_emb_key[s * 256 + c])) atomicMax(&g_arg[s * 256 + c], i);
}

// ---------------- emb coords ----------------
__global__ void embc_k(const int* __restrict__ ind) {
    __shared__ float rz[256], ry[256], rx[256];
    int s = blockIdx.x;
    int t = threadIdx.x;
    int idx = g_arg[s * 256 + t];
    int i = idx < 0 ? 0 : idx;
    int z = ind[i * 4 + 1], y = ind[i * 4 + 2], x = ind[i * 4 + 3];
    rz[t] = (float)(z / 40);
    ry[t] = (float)(y / 15);
    rx[t] = (float)(x / 16);
    __syncthreads();
    for (int o = 128; o > 0; o >>= 1) {
        if (t < o) { rz[t] += rz[t + o]; ry[t] += ry[t + o]; rx[t] += rx[t + o]; }
        __syncthreads();
    }
    if (t == 0) {
        g_embc[s * 3 + 0] = rz[0] * (1.f / 256.f) * 40.f;
        g_embc[s * 3 + 1] = ry[0] * (1.f / 256.f) * 15.f;
        g_embc[s * 3 + 2] = rx[0] * (1.f / 256.f) * 16.f;
    }
}

// ---------------- sine positional encoding ----------------
__device__ __forceinline__ float pe_val(float cz, float cy, float cx, int c) {
    if (c >= PEC) return 0.f;
    int axis = c / (2 * NF);
    int r = c - axis * (2 * NF);
    int j = r < NF ? r : r - NF;
    float coord = (axis == 0) ? cz : (axis == 1) ? cy : cx;
    float spd = (axis == 0) ? 480.f : (axis == 1) ? 360.f : 32.f;
    float tpow = powf(10000.f, (float)j * (1.f / (float)NF));
    float ang = coord / spd * 6.283185307179586f / tpow;
    return (r < NF) ? sinf(ang) : cosf(ang);
}

__global__ void buildq_k() {
    int s = blockIdx.x;
    int c = threadIdx.x;
    int rem = s % GQ;
    float cz = (float)((rem / (YD * XD)) * 8);
    float cy = (float)(((rem / XD) % YD) * 8);
    float cx = (float)((rem % XD) * 8);
    float base = g_mask_q[s] ? fdec(g_pool_key[(size_t)s * 256 + c]) : 0.f;
    float val = base + pe_val(cz, cy, cx, c);
    size_t idx = (size_t)s * 256 + c;
    g_qin[idx] = val;
    __nv_bfloat16 h, l;
    split_bf16(val, h, l);
    g_qinH[idx] = h;
    g_qinL[idx] = l;
}

__global__ void buildkv_k() {
    int s = blockIdx.x;
    int c = threadIdx.x;
    float cz = g_embc[s * 3 + 0];
    float cy = g_embc[s * 3 + 1];
    float cx = g_embc[s * 3 + 2];
    float base = g_mask_k[s] ? fdec(g_emb_key[s * 256 + c]) : 0.f;
    float val = base + pe_val(cz, cy, cx, c);
    __nv_bfloat16 h, l;
    split_bf16(val, h, l);
    g_kvH[s * 256 + c] = h;
    g_kvL[s * 256 + c] = l;
}

// ---------------- fused flash attention: scores + softmax + AV ----------------
#define APAD 40
#define BPAD 72
__global__ __launch_bounds__(128) void fattn_k(const int* __restrict__ maskk) {
    __shared__ __align__(16) __nv_bfloat16 sQ[2][64][APAD];   // [hi/lo][q][d]
    __shared__ __align__(16) __nv_bfloat16 sK[2][32][BPAD];   // [hi/lo][d][key64]
    __shared__ __align__(16) __nv_bfloat16 sV[2][64][APAD];   // [hi/lo][key][d]
    __shared__ int smask[GK];

    int t = threadIdx.x, wid = t >> 5, lane = t & 31;
    int bh = blockIdx.y, b = bh >> 3, h = bh & 7;
    int q0 = blockIdx.x * 64;

    // ---- load Q tile (pre-scaled, pre-split bf16) ----
    {
#pragma unroll
        for (int i = 0; i < 2; i++) {
            int op = t * 2 + i;
            int r = op >> 2, seg = op & 3;
            uint4 vh = make_uint4(0, 0, 0, 0), vl = vh;
            if (q0 + r < GQ) {
                size_t s = (size_t)(b * GQ + q0 + r) * 256 + h * 32 + seg * 8;
                vh = *(const uint4*)&g_qpH[s];
                vl = *(const uint4*)&g_qpL[s];
            }
            *(uint4*)&sQ[0][r][seg * 8] = vh;
            *(uint4*)&sQ[1][r][seg * 8] = vl;
        }
    }
    for (int i = t; i < GK; i += 128) smask[i] = maskk[b * GK + i];
    __syncthreads();

    // ---- Q fragments ----
    uint32_t qh[2][4], ql[2][4];
    {
        int arow = wid * 16 + (lane & 15);
#pragma unroll
        for (int s = 0; s < 2; s++) {
            int akc = s * 16 + ((lane & 16) ? 8 : 0);
            LDSM_X4(qh[s], sptr(&sQ[0][arow][akc]));
            LDSM_X4(ql[s], sptr(&sQ[1][arow][akc]));
        }
    }

    float m0r = -INFINITY, m1r = -INFINITY, l0 = 0.f, l1 = 0.f;
    float oacc[4][4] = {};
    int g = lane >> 2, tid4 = lane & 3;
    int bkr = lane & 15;
    int bsel = (lane & 16) ? 8 : 0;

    for (int c = 0; c < 9; c++) {
        {
            int d = t >> 2, ks = (t & 3) * 16;
            size_t src = (size_t)(bh * 32 + d) * 576 + c * 64 + ks;
            const uint4* sh = (const uint4*)&g_k16h[src];
            const uint4* sl = (const uint4*)&g_k16l[src];
            uint4* dh = (uint4*)&sK[0][d][ks];
            uint4* dl = (uint4*)&sK[1][d][ks];
            dh[0] = sh[0]; dh[1] = sh[1];
            dl[0] = sl[0]; dl[1] = sl[1];
        }
        {
            int key = t >> 1, ds = (t & 1) * 16;
            size_t src = (size_t)(bh * 576 + c * 64 + key) * 32 + ds;
            const uint4* sh = (const uint4*)&g_v16h[src];
            const uint4* sl = (const uint4*)&g_v16l[src];
            uint4* dh = (uint4*)&sV[0][key][ds];
            uint4* dl = (uint4*)&sV[1][key][ds];
            dh[0] = sh[0]; dh[1] = sh[1];
            dl[0] = sl[0]; dl[1] = sl[1];
        }
        __syncthreads();

        float acc[8][4] = {};
#pragma unroll
        for (int s = 0; s < 2; s++) {
#pragma unroll
            for (int j = 0; j < 4; j++) {
                uint32_t kh_[4], kl_[4];
                LDSM_X4_T(kh_, sptr(&sK[0][s * 16 + bkr][j * 16 + bsel]));
                LDSM_X4_T(kl_, sptr(&sK[1][s * 16 + bkr][j * 16 + bsel]));
                mma16816(acc[2 * j],     qh[s], kh_[0], kh_[1]);
                mma16816(acc[2 * j],     qh[s], kl_[0], kl_[1]);
                mma16816(acc[2 * j],     ql[s], kh_[0], kh_[1]);
                mma16816(acc[2 * j + 1], qh[s], kh_[2], kh_[3]);
                mma16816(acc[2 * j + 1], qh[s], kl_[2], kl_[3]);
                mma16816(acc[2 * j + 1], ql[s], kh_[2], kh_[3]);
            }
        }
#pragma unroll
        for (int j = 0; j < 8; j++) {
            int key = c * 64 + j * 8 + tid4 * 2;
            if (!smask[key])     { acc[j][0] = -1e9f; acc[j][2] = -1e9f; }
            if (!smask[key + 1]) { acc[j][1] = -1e9f; acc[j][3] = -1e9f; }
        }
        float mx0 = -INFINITY, mx1 = -INFINITY;
#pragma unroll
        for (int j = 0; j < 8; j++) {
            mx0 = fmaxf(mx0, fmaxf(acc[j][0], acc[j][1]));
            mx1 = fmaxf(mx1, fmaxf(acc[j][2], acc[j][3]));
        }
        mx0 = fmaxf(mx0, __shfl_xor_sync(0xFFFFFFFFu, mx0, 1));
        mx0 = fmaxf(mx0, __shfl_xor_sync(0xFFFFFFFFu, mx0, 2));
        mx1 = fmaxf(mx1, __shfl_xor_sync(0xFFFFFFFFu, mx1, 1));
        mx1 = fmaxf(mx1, __shfl_xor_sync(0xFFFFFFFFu, mx1, 2));
        float mn0 = fmaxf(m0r, mx0), mn1 = fmaxf(m1r, mx1);
        float rs0 = __expf(m0r - mn0), rs1 = __expf(m1r - mn1);
        float sum0 = 0.f, sum1 = 0.f;
#pragma unroll
        for (int j = 0; j < 8; j++) {
            acc[j][0] = __expf(acc[j][0] - mn0);
            acc[j][1] = __expf(acc[j][1] - mn0);
            acc[j][2] = __expf(acc[j][2] - mn1);
            acc[j][3] = __expf(acc[j][3] - mn1);
            sum0 += acc[j][0] + acc[j][1];
            sum1 += acc[j][2] + acc[j][3];
        }
        sum0 += __shfl_xor_sync(0xFFFFFFFFu, sum0, 1);
        sum0 += __shfl_xor_sync(0xFFFFFFFFu, sum0, 2);
        sum1 += __shfl_xor_sync(0xFFFFFFFFu, sum1, 1);
        sum1 += __shfl_xor_sync(0xFFFFFFFFu, sum1, 2);
        l0 = l0 * rs0 + sum0;
        l1 = l1 * rs1 + sum1;
#pragma unroll
        for (int dt = 0; dt < 4; dt++) {
            oacc[dt][0] *= rs0; oacc[dt][1] *= rs0;
            oacc[dt][2] *= rs1; oacc[dt][3] *= rs1;
        }
        m0r = mn0; m1r = mn1;

#pragma unroll
        for (int kt = 0; kt < 4; kt++) {
            uint32_t pha[4], pla[4];
            split2pack(acc[2 * kt][0],     acc[2 * kt][1],     pha[0], pla[0]);
            split2pack(acc[2 * kt][2],     acc[2 * kt][3],     pha[1], pla[1]);
            split2pack(acc[2 * kt + 1][0], acc[2 * kt + 1][1], pha[2], pla[2]);
            split2pack(acc[2 * kt + 1][2], acc[2 * kt + 1][3], pha[3], pla[3]);
#pragma unroll
            for (int dh2 = 0; dh2 < 2; dh2++) {
                uint32_t vh_[4], vl_[4];
                LDSM_X4_T(vh_, sptr(&sV[0][kt * 16 + bkr][dh2 * 16 + bsel]));
                LDSM_X4_T(vl_, sptr(&sV[1][kt * 16 + bkr][dh2 * 16 + bsel]));
                mma16816(oacc[dh2 * 2],     pha, vh_[0], vh_[1]);
                mma16816(oacc[dh2 * 2],     pha, vl_[0], vl_[1]);
                mma16816(oacc[dh2 * 2],     pla, vh_[0], vh_[1]);
                mma16816(oacc[dh2 * 2 + 1], pha, vh_[2], vh_[3]);
                mma16816(oacc[dh2 * 2 + 1], pha, vl_[2], vl_[3]);
                mma16816(oacc[dh2 * 2 + 1], pla, vh_[2], vh_[3]);
            }
        }
        __syncthreads();
    }

    // ---- finalize + split store ----
    float inv0 = 1.f / l0, inv1 = 1.f / l1;
    int qa = q0 + wid * 16 + g;
    int qb = qa + 8;
#pragma unroll
    for (int dt = 0; dt < 4; dt++) {
        int dim = h * 32 + dt * 8 + tid4 * 2;
        if (qa < GQ) {
            uint32_t hi, lo;
            split2pack(oacc[dt][0] * inv0, oacc[dt][1] * inv0, hi, lo);
            *(uint32_t*)&g_oaH[(size_t)(b * GQ + qa) * 256 + dim] = hi;
            *(uint32_t*)&g_oaL[(size_t)(b * GQ + qa) * 256 + dim] = lo;
        }
        if (qb < GQ) {
            uint32_t hi, lo;
            split2pack(oacc[dt][2] * inv1, oacc[dt][3] * inv1, hi, lo);
            *(uint32_t*)&g_oaH[(size_t)(b * GQ + qb) * 256 + dim] = hi;
            *(uint32_t*)&g_oaL[(size_t)(b * GQ + qb) * 256 + dim] = lo;
        }
    }
}

// ---------------- residual + LayerNorm ----------------
__global__ void ln_k(const float* __restrict__ qin, const float* __restrict__ o2,
                     const float* __restrict__ g, const float* __restrict__ bb,
                     float* __restrict__ out) {
    __shared__ float red[256];
    __shared__ float mu_s, var_s;
    int r = blockIdx.x;
    int c = threadIdx.x;
    float h = qin[(size_t)r * 256 + c] + o2[(size_t)r * 256 + c];
    red[c] = h;
    __syncthreads();
    for (int o = 128; o > 0; o >>= 1) {
        if (c < o) red[c] += red[c + o];
        __syncthreads();
    }
    if (c == 0) mu_s = red[0] * (1.f / 256.f);
    __syncthreads();
    float d = h - mu_s;
    red[c] = d * d;
    __syncthreads();
    for (int o = 128; o > 0; o >>= 1) {
        if (c < o) red[c] += red[c + o];
        __syncthreads();
    }
    if (c == 0) var_s = red[0] * (1.f / 256.f);
    __syncthreads();
    out[(size_t)r * 256 + c] = d * rsqrtf(var_s + 1e-5f) * g[c] + bb[c];
}

// ---------------- final gather + seg head ----------------
__global__ void head_k(const float* __restrict__ feat, const float* __restrict__ Wseg,
                       const float* __restrict__ bseg, float* __restrict__ out) {
    __shared__ float Ws[256 * NOUT];
    int t = threadIdx.x;
    for (int i = t; i < 256 * NOUT; i += 256) Ws[i] = Wseg[i];
    __syncthreads();
    int p = blockIdx.x * 8 + (t >> 5);
    int lane = t & 31;
    int sg = g_segq[p];
    float v[8];
#pragma unroll
    for (int r = 0; r < 8; r++) {
        int c = lane + 32 * r;
        v[r] = feat[(size_t)p * 256 + c] + g_mhca[(size_t)sg * 256 + c];
    }
#pragma unroll
    for (int j = 0; j < NOUT; j++) {
        float s = 0.f;
#pragma unroll
        for (int r = 0; r < 8; r++) s = fmaf(v[r], Ws[(lane + 32 * r) * NOUT + j], s);
#pragma unroll
        for (int o = 16; o; o >>= 1) s += __shfl_xor_sync(0xFFFFFFFFu, s, o);
        if (lane == 0) out[(size_t)p * NOUT + j] = s + bseg[j];
    }
}

// ---------------- host launch ----------------
static void* sym_addr(const void* symbol) {
    void* p = nullptr;
    cudaGetSymbolAddress(&p, symbol);
    return p;
}

extern "C" void kernel_launch(void* const* d_in, const int* in_sizes, int n_in,
                              void* d_out, int out_size) {
    const float* feat  = (const float*)d_in[0];
    const float* Wpool = (const float*)d_in[1];
    const float* bpool = (const float*)d_in[2];
    const float* Wemb  = (const float*)d_in[3];
    const float* bemb  = (const float*)d_in[4];
    const float* Wq    = (const float*)d_in[5];
    const float* bq    = (const float*)d_in[6];
    const float* Wk    = (const float*)d_in[7];
    const float* bk    = (const float*)d_in[8];
    const float* Wv    = (const float*)d_in[9];
    const float* bv    = (const float*)d_in[10];
    const float* Wo    = (const float*)d_in[11];
    const float* bo    = (const float*)d_in[12];
    const float* lng   = (const float*)d_in[13];
    const float* lnb   = (const float*)d_in[14];
    const float* Wseg  = (const float*)d_in[15];
    const float* bseg  = (const float*)d_in[16];
    const int*   ind   = (const int*)d_in[17];
    float* out = (float*)d_out;

    unsigned* p_pool_key = (unsigned*)sym_addr(g_pool_key);
    unsigned* p_emb_key  = (unsigned*)sym_addr(g_emb_key);
    int*      p_segq     = (int*)sym_addr(g_segq);
    int*      p_segk     = (int*)sym_addr(g_segk);
    int*      p_mask_k   = (int*)sym_addr(g_mask_k);
    float*    p_ef       = (float*)sym_addr(g_ef);
    float*    p_qin      = (float*)sym_addr(g_qin);
    float*    p_o2       = (float*)sym_addr(g_o2);
    float*    p_mhca     = (float*)sym_addr(g_mhca);
    __nv_bfloat16* p_featH = (__nv_bfloat16*)sym_addr(g_featH);
    __nv_bfloat16* p_featL = (__nv_bfloat16*)sym_addr(g_featL);
    __nv_bfloat16* p_wH    = (__nv_bfloat16*)sym_addr(g_wH);
    __nv_bfloat16* p_wL    = (__nv_bfloat16*)sym_addr(g_wL);
    __nv_bfloat16* p_qinH  = (__nv_bfloat16*)sym_addr(g_qinH);
    __nv_bfloat16* p_qinL  = (__nv_bfloat16*)sym_addr(g_qinL);
    __nv_bfloat16* p_kvH   = (__nv_bfloat16*)sym_addr(g_kvH);
    __nv_bfloat16* p_kvL   = (__nv_bfloat16*)sym_addr(g_kvL);
    __nv_bfloat16* p_qpH   = (__nv_bfloat16*)sym_addr(g_qpH);
    __nv_bfloat16* p_qpL   = (__nv_bfloat16*)sym_addr(g_qpL);
    __nv_bfloat16* p_oaH   = (__nv_bfloat16*)sym_addr(g_oaH);
    __nv_bfloat16* p_oaL   = (__nv_bfloat16*)sym_addr(g_oaL);
    __nv_bfloat16* p_k16h  = (__nv_bfloat16*)sym_addr(g_k16h);
    __nv_bfloat16* p_k16l  = (__nv_bfloat16*)sym_addr(g_k16l);
    __nv_bfloat16* p_v16h  = (__nv_bfloat16*)sym_addr(g_v16h);
    __nv_bfloat16* p_v16l  = (__nv_bfloat16*)sym_addr(g_v16l);

    cudaFuncSetAttribute(bf_gemm<10>, cudaFuncAttributeMaxDynamicSharedMemorySize, GEMM_SMEM);
    cudaFuncSetAttribute(bf_gemm<0>,  cudaFuncAttributeMaxDynamicSharedMemorySize, GEMM_SMEM);
    cudaFuncSetAttribute(bf_gemm<3>,  cudaFuncAttributeMaxDynamicSharedMemorySize, GEMM_SMEM);
    cudaFuncSetAttribute(bf_gemm<4>,  cudaFuncAttributeMaxDynamicSharedMemorySize, GEMM_SMEM);
    cudaFuncSetAttribute(bf_gemm<5>,  cudaFuncAttributeMaxDynamicSharedMemorySize, GEMM_SMEM);

    const float qscale = 0.17677669529663687f;  // 1/sqrt(32)

    // 1. init + prep + splits
    init_k<<<(SQ * DIM + 255) / 256, 256>>>();
    prep_k<<<(NP + 255) / 256, 256>>>(ind);
    split_feat_k<<<(NP * DIM / 4 + 255) / 256, 256>>>(feat);
    split_w_k<<<(6 * 16384 + 255) / 256, 256>>>(Wpool, Wemb, Wq, Wk, Wv, Wo);
    // 2. fused pool+emb GEMM (scatter-max + ef store)
    bf_gemm<10><<<dim3(8, (NP + 127) / 128), 256, GEMM_SMEM>>>(
        p_featH, p_featL,
        p_wH + 0 * 65536, p_wL + 0 * 65536, bpool,
        p_wH + 1 * 65536, p_wL + 1 * 65536, bemb,
        p_ef, p_pool_key, p_segq, p_emb_key, p_segk,
        nullptr, nullptr, 0.f, NP);
    // 3. argmax + coords
    argmax_k<<<(NP * DIM) / 256, 256>>>();
    embc_k<<<SK, 256>>>(ind);
    // 4. PE grids (fp32 + split)
    buildq_k<<<SQ, 256>>>();
    buildkv_k<<<SK, 256>>>();
    // 5. projections
    bf_gemm<3><<<dim3(4, (SQ + 127) / 128), 256, GEMM_SMEM>>>(
        p_qinH, p_qinL, p_wH + 2 * 65536, p_wL + 2 * 65536, bq,
        nullptr, nullptr, nullptr, nullptr, nullptr, nullptr, nullptr, nullptr,
        p_qpH, p_qpL, qscale, SQ);
    bf_gemm<4><<<dim3(4, SK / 128), 256, GEMM_SMEM>>>(
        p_kvH, p_kvL, p_wH + 3 * 65536, p_wL + 3 * 65536, bk,
        nullptr, nullptr, nullptr, nullptr, nullptr, nullptr, nullptr, nullptr,
        p_k16h, p_k16l, 0.f, SK);
    bf_gemm<5><<<dim3(4, SK / 128), 256, GEMM_SMEM>>>(
        p_kvH, p_kvL, p_wH + 4 * 65536, p_wL + 4 * 65536, bv,
        nullptr, nullptr, nullptr, nullptr, nullptr, nullptr, nullptr, nullptr,
        p_v16h, p_v16l, 0.f, SK);
    // 6. fused flash attention
    fattn_k<<<dim3((GQ + 63) / 64, BATCH * NH), 128>>>(p_mask_k);
    // 7. output projection + residual + LN
    bf_gemm<0><<<dim3(4, (SQ + 127) / 128), 256, GEMM_SMEM>>>(
        p_oaH, p_oaL, p_wH + 5 * 65536, p_wL + 5 * 65536, bo,
        nullptr, nullptr, nullptr, p_o2, nullptr, nullptr, nullptr, nullptr,
        nullptr, nullptr, 0.f, SQ);
    ln_k<<<SQ, 256>>>(p_qin, p_o2, lng, lnb, p_mhca);
    // 8. gather + seg head
    head_k<<<NP / 8, 256>>>(feat, Wseg, bseg, out);
}

// round 7
// speedup vs baseline: 2.1482x; 1.0943x over previous
#include <cuda_runtime.h>
#include <cuda_bf16.h>
#include <math.h>
#include <stdint.h>

// ---------------- problem constants ----------------
#define NP   120000
#define DIM  256
#define BATCH 2
#define NH   8
#define NOUT 20
#define ZD 60
#define YD 45
#define XD 4
#define GQ 10800
#define SQ 21600
#define ZE 12
#define YE 24
#define XE 2
#define GK 576
#define SK 1152
#define NF 42
#define PEC 252

// ---------------- scratch ----------------
__device__ unsigned g_pool_key[SQ * DIM];
__device__ unsigned g_emb_key[SK * DIM];
__device__ int      g_mask_q[SQ];
__device__ int      g_mask_k[SK];
__device__ int      g_segq[NP];
__device__ int      g_segk[NP];
__device__ float    g_ef[(size_t)NP * DIM];
__device__ int      g_arg[SK * DIM];
__device__ float    g_embc[SK * 3];
__device__ float    g_qin[(size_t)SQ * DIM];
__device__ float    g_o2[(size_t)SQ * DIM];
__device__ float    g_mhca[(size_t)SQ * DIM];
__device__ float    g_invt[64];
__device__ __nv_bfloat16 g_featH[(size_t)NP * DIM];
__device__ __nv_bfloat16 g_featL[(size_t)NP * DIM];
__device__ __nv_bfloat16 g_wH[6 * 65536];
__device__ __nv_bfloat16 g_wL[6 * 65536];
__device__ __nv_bfloat16 g_qinH[(size_t)SQ * DIM];
__device__ __nv_bfloat16 g_qinL[(size_t)SQ * DIM];
__device__ __nv_bfloat16 g_kvH[SK * DIM];
__device__ __nv_bfloat16 g_kvL[SK * DIM];
__device__ __nv_bfloat16 g_qpH[(size_t)SQ * DIM];
__device__ __nv_bfloat16 g_qpL[(size_t)SQ * DIM];
__device__ __nv_bfloat16 g_oaH[(size_t)SQ * DIM];
__device__ __nv_bfloat16 g_oaL[(size_t)SQ * DIM];
__device__ __nv_bfloat16 g_k16h[16 * 32 * 576];
__device__ __nv_bfloat16 g_k16l[16 * 32 * 576];
__device__ __nv_bfloat16 g_v16h[16 * 576 * 32];
__device__ __nv_bfloat16 g_v16l[16 * 576 * 32];

__device__ __forceinline__ unsigned fenc(float f) {
    unsigned u = __float_as_uint(f);
    return (u & 0x80000000u) ? ~u : (u | 0x80000000u);
}
__device__ __forceinline__ float fdec(unsigned k) {
    return __uint_as_float((k & 0x80000000u) ? (k ^ 0x80000000u) : ~k);
}

// ================= warp MMA helpers =================
__device__ __forceinline__ uint32_t sptr(const void* p) {
    return (uint32_t)__cvta_generic_to_shared(p);
}

#define LDSM_X4(r, addr) \
    asm volatile("ldmatrix.sync.aligned.m8n8.x4.shared.b16 {%0,%1,%2,%3}, [%4];" \
        : "=r"((r)[0]), "=r"((r)[1]), "=r"((r)[2]), "=r"((r)[3]) : "r"(addr))

#define LDSM_X4_T(r, addr) \
    asm volatile("ldmatrix.sync.aligned.m8n8.x4.trans.shared.b16 {%0,%1,%2,%3}, [%4];" \
        : "=r"((r)[0]), "=r"((r)[1]), "=r"((r)[2]), "=r"((r)[3]) : "r"(addr))

__device__ __forceinline__ void mma16816(float* c, const uint32_t* a, uint32_t b0, uint32_t b1) {
    asm volatile(
        "mma.sync.aligned.m16n8k16.row.col.f32.bf16.bf16.f32 "
        "{%0,%1,%2,%3}, {%4,%5,%6,%7}, {%8,%9}, {%0,%1,%2,%3};"
        : "+f"(c[0]), "+f"(c[1]), "+f"(c[2]), "+f"(c[3])
        : "r"(a[0]), "r"(a[1]), "r"(a[2]), "r"(a[3]), "r"(b0), "r"(b1));
}

#define CP16(dst, src) \
    asm volatile("cp.async.cg.shared.global [%0], [%1], 16;\n" :: "r"(dst), "l"(src))
#define CP_COMMIT asm volatile("cp.async.commit_group;\n" ::: "memory")
#define CP_WAIT1 asm volatile("cp.async.wait_group 1;\n" ::: "memory")
#define CP_WAIT0 asm volatile("cp.async.wait_group 0;\n" ::: "memory")

__device__ __forceinline__ void split_bf16(float v, __nv_bfloat16& h, __nv_bfloat16& l) {
    h = __float2bfloat16(v);
    l = __float2bfloat16(v - __bfloat162float(h));
}

__device__ __forceinline__ void split2pack(float a, float b, uint32_t& hi, uint32_t& lo) {
    __nv_bfloat16 ha = __float2bfloat16(a), hb = __float2bfloat16(b);
    __nv_bfloat16 la = __float2bfloat16(a - __bfloat162float(ha));
    __nv_bfloat16 lb = __float2bfloat16(b - __bfloat162float(hb));
    __nv_bfloat162 th(ha, hb), tl(la, lb);
    hi = *(uint32_t*)&th;
    lo = *(uint32_t*)&tl;
}

// ---------------- split kernels ----------------
__global__ void split_feat_k(const float* __restrict__ src) {
    size_t i = (size_t)blockIdx.x * 256 + threadIdx.x;
    if (i * 4 >= (size_t)NP * DIM) return;
    float4 v = ((const float4*)src)[i];
    __nv_bfloat16 hx, lx, hy, ly, hz, lz, hw, lw;
    split_bf16(v.x, hx, lx); split_bf16(v.y, hy, ly);
    split_bf16(v.z, hz, lz); split_bf16(v.w, hw, lw);
    ((__nv_bfloat162*)g_featH)[i * 2]     = __nv_bfloat162(hx, hy);
    ((__nv_bfloat162*)g_featH)[i * 2 + 1] = __nv_bfloat162(hz, hw);
    ((__nv_bfloat162*)g_featL)[i * 2]     = __nv_bfloat162(lx, ly);
    ((__nv_bfloat162*)g_featL)[i * 2 + 1] = __nv_bfloat162(lz, lw);
}

__global__ void split_w_k(const float* __restrict__ w0, const float* __restrict__ w1,
                          const float* __restrict__ w2, const float* __restrict__ w3,
                          const float* __restrict__ w4, const float* __restrict__ w5) {
    int i = blockIdx.x * 256 + threadIdx.x;
    if (i >= 6 * 16384) return;
    int which = i >> 14;
    int off = i & 16383;
    const float* src = which == 0 ? w0 : which == 1 ? w1 : which == 2 ? w2
                     : which == 3 ? w3 : which == 4 ? w4 : w5;
    float4 v = ((const float4*)src)[off];
    __nv_bfloat16 hx, lx, hy, ly, hz, lz, hw, lw;
    split_bf16(v.x, hx, lx); split_bf16(v.y, hy, ly);
    split_bf16(v.z, hz, lz); split_bf16(v.w, hw, lw);
    ((__nv_bfloat162*)g_wH)[i * 2]     = __nv_bfloat162(hx, hy);
    ((__nv_bfloat162*)g_wH)[i * 2 + 1] = __nv_bfloat162(hz, hw);
    ((__nv_bfloat162*)g_wL)[i * 2]     = __nv_bfloat162(lx, ly);
    ((__nv_bfloat162*)g_wL)[i * 2 + 1] = __nv_bfloat162(lz, lw);
}

__global__ void pe_init_k() {
    int j = threadIdx.x;
    if (j < NF) g_invt[j] = 1.0f / powf(10000.0f, (float)j / (float)NF);
}

// ================= pipelined bf16x3 MMA GEMM =====================
// CTA tile 128m x 128n; 8 warps 2x4, warp tile 64x32; 2-stage cp.async; K chunk 32.
// Grid x: column half (c0 = x*128); MODE 10: x>>1 = matrix (0 pool, 1 emb), x&1 = col half.
#define AP 40
#define BP 136
#define SA_BYTES (2 * 2 * 128 * AP * 2)
#define SB_BYTES (2 * 2 * 32 * BP * 2)
#define GEMM_SMEM (SA_BYTES + SB_BYTES)

__device__ __forceinline__ __nv_bfloat16* pA(__nv_bfloat16* b, int st, int mat, int r) {
    return b + ((st * 2 + mat) * 128 + r) * AP;
}
__device__ __forceinline__ __nv_bfloat16* pB(__nv_bfloat16* b, int st, int mat, int r) {
    return b + ((st * 2 + mat) * 32 + r) * BP;
}

template <int MODE>
__global__ __launch_bounds__(256, 2) void bf_gemm(
    const __nv_bfloat16* __restrict__ Ah, const __nv_bfloat16* __restrict__ Al,
    const __nv_bfloat16* __restrict__ WhA, const __nv_bfloat16* __restrict__ WlA,
    const float* __restrict__ biasA,
    const __nv_bfloat16* __restrict__ WhB, const __nv_bfloat16* __restrict__ WlB,
    const float* __restrict__ biasB,
    float* __restrict__ Cout,
    unsigned* __restrict__ keyP, const int* __restrict__ segP,
    unsigned* __restrict__ keyE, const int* __restrict__ segE,
    __nv_bfloat16* __restrict__ outH, __nv_bfloat16* __restrict__ outL,
    float scale, int M)
{
    extern __shared__ char dsm[];
    __nv_bfloat16* sA = (__nv_bfloat16*)dsm;
    __nv_bfloat16* sB = (__nv_bfloat16*)(dsm + SA_BYTES);

    int t = threadIdx.x, wid = t >> 5, lane = t & 31;
    int wm = wid >> 2, wn = wid & 3;
    int m0 = blockIdx.y * 128;

    bool isPool = false;
    const __nv_bfloat16 *Whp = WhA, *Wlp = WlA;
    const float* bp = biasA;
    int c0;
    if (MODE == 10) {
        isPool = ((blockIdx.x >> 1) == 0);
        if (!isPool) { Whp = WhB; Wlp = WlB; bp = biasB; }
        c0 = (blockIdx.x & 1) * 128;
    } else {
        c0 = blockIdx.x * 128;
    }

    float acc[4][4][4] = {};

    auto copyA = [&](int st, int ch) {
        int k0 = ch * 32;
#pragma unroll
        for (int i = 0; i < 2; i++) {
            int op = t * 2 + i;
            int r = op >> 2, seg = op & 3;
            int rowc = m0 + r;
            if (rowc >= M) rowc = M - 1;
            size_t src = (size_t)rowc * 256 + k0 + seg * 8;
            CP16(sptr(pA(sA, st, 0, r) + seg * 8), Ah + src);
            CP16(sptr(pA(sA, st, 1, r) + seg * 8), Al + src);
        }
    };
    auto copyB = [&](int st, int ch) {
        int k0 = ch * 32;
        int r = t >> 3;
#pragma unroll
        for (int q = 0; q < 2; q++) {
            int seg = (t & 7) + q * 8;
            size_t src = (size_t)(k0 + r) * 256 + c0 + seg * 8;
            CP16(sptr(pB(sB, st, 0, r) + seg * 8), Whp + src);
            CP16(sptr(pB(sB, st, 1, r) + seg * 8), Wlp + src);
        }
    };

    copyA(0, 0);
    copyB(0, 0);
    CP_COMMIT;

    for (int ch = 0; ch < 8; ch++) {
        if (ch < 7) {
            copyA((ch + 1) & 1, ch + 1);
            copyB((ch + 1) & 1, ch + 1);
            CP_COMMIT;
            CP_WAIT1;
        } else {
            CP_WAIT0;
        }
        __syncthreads();
        int st = ch & 1;
#pragma unroll
        for (int ks = 0; ks < 2; ks++) {
            int arow = wm * 64 + (lane & 15);
            int akc = ks * 16 + ((lane & 16) ? 8 : 0);
            int bkr = ks * 16 + (lane & 15);
            int bnc = wn * 32 + ((lane & 16) ? 8 : 0);

            uint32_t af[4][4], bh[8], bl[8];
#pragma unroll
            for (int mt = 0; mt < 4; mt++)
                LDSM_X4(af[mt], sptr(pA(sA, st, 0, arow + mt * 16) + akc));
            LDSM_X4_T(bh,     sptr(pB(sB, st, 0, bkr) + bnc));
            LDSM_X4_T(bh + 4, sptr(pB(sB, st, 0, bkr) + bnc + 16));
            LDSM_X4_T(bl,     sptr(pB(sB, st, 1, bkr) + bnc));
            LDSM_X4_T(bl + 4, sptr(pB(sB, st, 1, bkr) + bnc + 16));

#pragma unroll
            for (int mt = 0; mt < 4; mt++) {
#pragma unroll
                for (int nt = 0; nt < 4; nt++) {
                    mma16816(acc[mt][nt], af[mt], bh[nt * 2], bh[nt * 2 + 1]);
                    mma16816(acc[mt][nt], af[mt], bl[nt * 2], bl[nt * 2 + 1]);
                }
            }
#pragma unroll
            for (int mt = 0; mt < 4; mt++)
                LDSM_X4(af[mt], sptr(pA(sA, st, 1, arow + mt * 16) + akc));
#pragma unroll
            for (int mt = 0; mt < 4; mt++) {
#pragma unroll
                for (int nt = 0; nt < 4; nt++)
                    mma16816(acc[mt][nt], af[mt], bh[nt * 2], bh[nt * 2 + 1]);
            }
        }
        __syncthreads();
    }

    // ---- epilogue ----
    int g = lane >> 2, tid4 = lane & 3;
#pragma unroll
    for (int mt = 0; mt < 4; mt++) {
#pragma unroll
        for (int nt = 0; nt < 4; nt++) {
            int coln = c0 + wn * 32 + nt * 8 + tid4 * 2;
            float b0 = bp[coln], b1 = bp[coln + 1];
#pragma unroll
            for (int half = 0; half < 2; half++) {
                int m = m0 + wm * 64 + mt * 16 + g + half * 8;
                if (m >= M) continue;
                float v0 = acc[mt][nt][half * 2 + 0] + b0;
                float v1 = acc[mt][nt][half * 2 + 1] + b1;
                if (MODE == 0) {
                    Cout[(size_t)m * 256 + coln]     = v0;
                    Cout[(size_t)m * 256 + coln + 1] = v1;
                } else if (MODE == 10) {
                    if (isPool) {
                        int sg = segP[m];
                        atomicMax(&keyP[sg * 256 + coln],     fenc(v0));
                        atomicMax(&keyP[sg * 256 + coln + 1], fenc(v1));
                    } else {
                        Cout[(size_t)m * 256 + coln]     = v0;
                        Cout[(size_t)m * 256 + coln + 1] = v1;
                        int sg = segE[m];
                        atomicMax(&keyE[sg * 256 + coln],     fenc(v0));
                        atomicMax(&keyE[sg * 256 + coln + 1], fenc(v1));
                    }
                } else if (MODE == 3) {
                    uint32_t hi, lo;
                    split2pack(v0 * scale, v1 * scale, hi, lo);
                    *(uint32_t*)&outH[(size_t)m * 256 + coln] = hi;
                    *(uint32_t*)&outL[(size_t)m * 256 + coln] = lo;
                } else if (MODE == 4) {
                    int b_ = m / 576, key = m - b_ * 576;
                    int hh = coln >> 5, d = coln & 31;
                    __nv_bfloat16 H, L;
                    split_bf16(v0, H, L);
                    size_t dst0 = (size_t)((b_ * 8 + hh) * 32 + d) * 576 + key;
                    outH[dst0] = H; outL[dst0] = L;
                    split_bf16(v1, H, L);
                    outH[dst0 + 576] = H; outL[dst0 + 576] = L;
                } else if (MODE == 5) {
                    int b_ = m / 576, key = m - b_ * 576;
                    int hh = coln >> 5, d = coln & 31;
                    __nv_bfloat16 H, L;
                    size_t dst0 = ((size_t)(b_ * 8 + hh) * 576 + key) * 32 + d;
                    split_bf16(v0, H, L);
                    outH[dst0] = H; outL[dst0] = L;
                    split_bf16(v1, H, L);
                    outH[dst0 + 1] = H; outL[dst0 + 1] = L;
                }
            }
        }
    }
}

// ---------------- per-point segment ids + occupancy masks ----------------
__global__ void prep_k(const int* __restrict__ ind) {
    int i = blockIdx.x * 256 + threadIdx.x;
    if (i >= NP) return;
    int b = ind[i * 4 + 0];
    int z = ind[i * 4 + 1];
    int y = ind[i * 4 + 2];
    int x = ind[i * 4 + 3];
    int sq = ((b * ZD + z / 8) * YD + y / 8) * XD + x / 8;
    int sk = ((b * ZE + z / 40) * YE + y / 15) * XE + x / 16;
    g_segq[i] = sq;
    g_segk[i] = sk;
    g_mask_q[sq] = 1;
    g_mask_k[sk] = 1;
}

// ---------------- per-channel argmax ----------------
__global__ void argmax_k() {
    size_t idx = (size_t)blockIdx.x * 256 + threadIdx.x;
    if (idx >= (size_t)NP * DIM) return;
    int i = (int)(idx >> 8);
    int c = (int)(idx & 255);
    float v = g_ef[idx];
    int s = g_segk[i];
    if (v == fdec(g_emb_key[s * 256 + c])) atomicMax(&g_arg[s * 256 + c], i);
}

// ---------------- emb coords ----------------
__global__ void embc_k(const int* __restrict__ ind) {
    __shared__ float rz[256], ry[256], rx[256];
    int s = blockIdx.x;
    int t = threadIdx.x;
    int idx = g_arg[s * 256 + t];
    int i = idx < 0 ? 0 : idx;
    int z = ind[i * 4 + 1], y = ind[i * 4 + 2], x = ind[i * 4 + 3];
    rz[t] = (float)(z / 40);
    ry[t] = (float)(y / 15);
    rx[t] = (float)(x / 16);
    __syncthreads();
    for (int o = 128; o > 0; o >>= 1) {
        if (t < o) { rz[t] += rz[t + o]; ry[t] += ry[t + o]; rx[t] += rx[t + o]; }
        __syncthreads();
    }
    if (t == 0) {
        g_embc[s * 3 + 0] = rz[0] * (1.f / 256.f) * 40.f;
        g_embc[s * 3 + 1] = ry[0] * (1.f / 256.f) * 15.f;
        g_embc[s * 3 + 2] = rx[0] * (1.f / 256.f) * 16.f;
    }
}

// ---------------- sine PE (table + fast intrinsics) ----------------
__device__ __forceinline__ float pe_val(float cz, float cy, float cx, int c) {
    if (c >= PEC) return 0.f;
    int axis = c / (2 * NF);
    int r = c - axis * (2 * NF);
    int j = r < NF ? r : r - NF;
    float coord = (axis == 0) ? cz : (axis == 1) ? cy : cx;
    float spd = (axis == 0) ? 480.f : (axis == 1) ? 360.f : 32.f;
    float ang = coord / spd * 6.283185307179586f * g_invt[j];
    return (r < NF) ? __sinf(ang) : __cosf(ang);
}

__global__ void buildq_k() {
    int s = blockIdx.x;
    int c = threadIdx.x;
    int rem = s % GQ;
    float cz = (float)((rem / (YD * XD)) * 8);
    float cy = (float)(((rem / XD) % YD) * 8);
    float cx = (float)((rem % XD) * 8);
    float base = g_mask_q[s] ? fdec(g_pool_key[(size_t)s * 256 + c]) : 0.f;
    float val = base + pe_val(cz, cy, cx, c);
    size_t idx = (size_t)s * 256 + c;
    g_qin[idx] = val;
    __nv_bfloat16 h, l;
    split_bf16(val, h, l);
    g_qinH[idx] = h;
    g_qinL[idx] = l;
}

__global__ void buildkv_k() {
    int s = blockIdx.x;
    int c = threadIdx.x;
    float cz = g_embc[s * 3 + 0];
    float cy = g_embc[s * 3 + 1];
    float cx = g_embc[s * 3 + 2];
    float base = g_mask_k[s] ? fdec(g_emb_key[s * 256 + c]) : 0.f;
    float val = base + pe_val(cz, cy, cx, c);
    __nv_bfloat16 h, l;
    split_bf16(val, h, l);
    g_kvH[s * 256 + c] = h;
    g_kvL[s * 256 + c] = l;
}

// ---------------- fused flash attention, 256 threads / 128 q rows ----------------
#define QPAD 40
#define KPAD 72
__global__ __launch_bounds__(256) void fattn_k(const int* __restrict__ maskk) {
    __shared__ __align__(16) __nv_bfloat16 sQ[2][128][QPAD];
    __shared__ __align__(16) __nv_bfloat16 sK[2][32][KPAD];
    __shared__ __align__(16) __nv_bfloat16 sV[2][64][QPAD];
    __shared__ int smask[GK];

    int t = threadIdx.x, wid = t >> 5, lane = t & 31;
    int bh = blockIdx.y, b = bh >> 3, h = bh & 7;
    int q0 = blockIdx.x * 128;

    {
#pragma unroll
        for (int i = 0; i < 2; i++) {
            int op = t * 2 + i;
            int r = op >> 2, seg = op & 3;
            uint4 vh = make_uint4(0, 0, 0, 0), vl = vh;
            if (q0 + r < GQ) {
                size_t s = (size_t)(b * GQ + q0 + r) * 256 + h * 32 + seg * 8;
                vh = *(const uint4*)&g_qpH[s];
                vl = *(const uint4*)&g_qpL[s];
            }
            *(uint4*)&sQ[0][r][seg * 8] = vh;
            *(uint4*)&sQ[1][r][seg * 8] = vl;
        }
    }
    for (int i = t; i < GK; i += 256) smask[i] = maskk[b * GK + i];
    __syncthreads();

    uint32_t qh[2][4], ql[2][4];
    {
        int arow = wid * 16 + (lane & 15);
#pragma unroll
        for (int s = 0; s < 2; s++) {
            int akc = s * 16 + ((lane & 16) ? 8 : 0);
            LDSM_X4(qh[s], sptr(&sQ[0][arow][akc]));
            LDSM_X4(ql[s], sptr(&sQ[1][arow][akc]));
        }
    }

    float m0r = -INFINITY, m1r = -INFINITY, l0 = 0.f, l1 = 0.f;
    float oacc[4][4] = {};
    int g = lane >> 2, tid4 = lane & 3;
    int bkr = lane & 15;
    int bsel = (lane & 16) ? 8 : 0;

    for (int c = 0; c < 9; c++) {
        {
            int d = t >> 3, ks = (t & 7) * 8;
            size_t src = (size_t)(bh * 32 + d) * 576 + c * 64 + ks;
            *(uint4*)&sK[0][d][ks] = *(const uint4*)&g_k16h[src];
            *(uint4*)&sK[1][d][ks] = *(const uint4*)&g_k16l[src];
        }
        {
            int key = t >> 2, ds = (t & 3) * 8;
            size_t src = (size_t)(bh * 576 + c * 64 + key) * 32 + ds;
            *(uint4*)&sV[0][key][ds] = *(const uint4*)&g_v16h[src];
            *(uint4*)&sV[1][key][ds] = *(const uint4*)&g_v16l[src];
        }
        __syncthreads();

        float acc[8][4] = {};
#pragma unroll
        for (int s = 0; s < 2; s++) {
#pragma unroll
            for (int j = 0; j < 4; j++) {
                uint32_t kh_[4], kl_[4];
                LDSM_X4_T(kh_, sptr(&sK[0][s * 16 + bkr][j * 16 + bsel]));
                LDSM_X4_T(kl_, sptr(&sK[1][s * 16 + bkr][j * 16 + bsel]));
                mma16816(acc[2 * j],     qh[s], kh_[0], kh_[1]);
                mma16816(acc[2 * j],     qh[s], kl_[0], kl_[1]);
                mma16816(acc[2 * j],     ql[s], kh_[0], kh_[1]);
                mma16816(acc[2 * j + 1], qh[s], kh_[2], kh_[3]);
                mma16816(acc[2 * j + 1], qh[s], kl_[2], kl_[3]);
                mma16816(acc[2 * j + 1], ql[s], kh_[2], kh_[3]);
            }
        }
#pragma unroll
        for (int j = 0; j < 8; j++) {
            int key = c * 64 + j * 8 + tid4 * 2;
            if (!smask[key])     { acc[j][0] = -1e9f; acc[j][2] = -1e9f; }
            if (!smask[key + 1]) { acc[j][1] = -1e9f; acc[j][3] = -1e9f; }
        }
        float mx0 = -INFINITY, mx1 = -INFINITY;
#pragma unroll
        for (int j = 0; j < 8; j++) {
            mx0 = fmaxf(mx0, fmaxf(acc[j][0], acc[j][1]));
            mx1 = fmaxf(mx1, fmaxf(acc[j][2], acc[j][3]));
        }
        mx0 = fmaxf(mx0, __shfl_xor_sync(0xFFFFFFFFu, mx0, 1));
        mx0 = fmaxf(mx0, __shfl_xor_sync(0xFFFFFFFFu, mx0, 2));
        mx1 = fmaxf(mx1, __shfl_xor_sync(0xFFFFFFFFu, mx1, 1));
        mx1 = fmaxf(mx1, __shfl_xor_sync(0xFFFFFFFFu, mx1, 2));
        float mn0 = fmaxf(m0r, mx0), mn1 = fmaxf(m1r, mx1);
        float rs0 = __expf(m0r - mn0), rs1 = __expf(m1r - mn1);
        float sum0 = 0.f, sum1 = 0.f;
#pragma unroll
        for (int j = 0; j < 8; j++) {
            acc[j][0] = __expf(acc[j][0] - mn0);
            acc[j][1] = __expf(acc[j][1] - mn0);
            acc[j][2] = __expf(acc[j][2] - mn1);
            acc[j][3] = __expf(acc[j][3] - mn1);
            sum0 += acc[j][0] + acc[j][1];
            sum1 += acc[j][2] + acc[j][3];
        }
        sum0 += __shfl_xor_sync(0xFFFFFFFFu, sum0, 1);
        sum0 += __shfl_xor_sync(0xFFFFFFFFu, sum0, 2);
        sum1 += __shfl_xor_sync(0xFFFFFFFFu, sum1, 1);
        sum1 += __shfl_xor_sync(0xFFFFFFFFu, sum1, 2);
        l0 = l0 * rs0 + sum0;
        l1 = l1 * rs1 + sum1;
#pragma unroll
        for (int dt = 0; dt < 4; dt++) {
            oacc[dt][0] *= rs0; oacc[dt][1] *= rs0;
            oacc[dt][2] *= rs1; oacc[dt][3] *= rs1;
        }
        m0r = mn0; m1r = mn1;

#pragma unroll
        for (int kt = 0; kt < 4; kt++) {
            uint32_t pha[4], pla[4];
            split2pack(acc[2 * kt][0],     acc[2 * kt][1],     pha[0], pla[0]);
            split2pack(acc[2 * kt][2],     acc[2 * kt][3],     pha[1], pla[1]);
            split2pack(acc[2 * kt + 1][0], acc[2 * kt + 1][1], pha[2], pla[2]);
            split2pack(acc[2 * kt + 1][2], acc[2 * kt + 1][3], pha[3], pla[3]);
#pragma unroll
            for (int dh2 = 0; dh2 < 2; dh2++) {
                uint32_t vh_[4], vl_[4];
                LDSM_X4_T(vh_, sptr(&sV[0][kt * 16 + bkr][dh2 * 16 + bsel]));
                LDSM_X4_T(vl_, sptr(&sV[1][kt * 16 + bkr][dh2 * 16 + bsel]));
                mma16816(oacc[dh2 * 2],     pha, vh_[0], vh_[1]);
                mma16816(oacc[dh2 * 2],     pha, vl_[0], vl_[1]);
                mma16816(oacc[dh2 * 2],     pla, vh_[0], vh_[1]);
                mma16816(oacc[dh2 * 2 + 1], pha, vh_[2], vh_[3]);
                mma16816(oacc[dh2 * 2 + 1], pha, vl_[2], vl_[3]);
                mma16816(oacc[dh2 * 2 + 1], pla, vh_[2], vh_[3]);
            }
        }
        __syncthreads();
    }

    float inv0 = 1.f / l0, inv1 = 1.f / l1;
    int qa = q0 + wid * 16 + g;
    int qb = qa + 8;
#pragma unroll
    for (int dt = 0; dt < 4; dt++) {
        int dim = h * 32 + dt * 8 + tid4 * 2;
        if (qa < GQ) {
            uint32_t hi, lo;
            split2pack(oacc[dt][0] * inv0, oacc[dt][1] * inv0, hi, lo);
            *(uint32_t*)&g_oaH[(size_t)(b * GQ + qa) * 256 + dim] = hi;
            *(uint32_t*)&g_oaL[(size_t)(b * GQ + qa) * 256 + dim] = lo;
        }
        if (qb < GQ) {
            uint32_t hi, lo;
            split2pack(oacc[dt][2] * inv1, oacc[dt][3] * inv1, hi, lo);
            *(uint32_t*)&g_oaH[(size_t)(b * GQ + qb) * 256 + dim] = hi;
            *(uint32_t*)&g_oaL[(size_t)(b * GQ + qb) * 256 + dim] = lo;
        }
    }
}

// ---------------- residual + LayerNorm ----------------
__global__ void ln_k(const float* __restrict__ qin, const float* __restrict__ o2,
                     const float* __restrict__ g, const float* __restrict__ bb,
                     float* __restrict__ out) {
    __shared__ float red[256];
    __shared__ float mu_s, var_s;
    int r = blockIdx.x;
    int c = threadIdx.x;
    float h = qin[(size_t)r * 256 + c] + o2[(size_t)r * 256 + c];
    red[c] = h;
    __syncthreads();
    for (int o = 128; o > 0; o >>= 1) {
        if (c < o) red[c] += red[c + o];
        __syncthreads();
    }
    if (c == 0) mu_s = red[0] * (1.f / 256.f);
    __syncthreads();
    float d = h - mu_s;
    red[c] = d * d;
    __syncthreads();
    for (int o = 128; o > 0; o >>= 1) {
        if (c < o) red[c] += red[c + o];
        __syncthreads();
    }
    if (c == 0) var_s = red[0] * (1.f / 256.f);
    __syncthreads();
    out[(size_t)r * 256 + c] = d * rsqrtf(var_s + 1e-5f) * g[c] + bb[c];
}

// ---------------- final gather + seg head ----------------
__global__ void head_k(const float* __restrict__ feat, const float* __restrict__ Wseg,
                       const float* __restrict__ bseg, float* __restrict__ out) {
    __shared__ float Ws[256 * NOUT];
    int t = threadIdx.x;
    for (int i = t; i < 256 * NOUT; i += 256) Ws[i] = Wseg[i];
    __syncthreads();
    int p = blockIdx.x * 8 + (t >> 5);
    int lane = t & 31;
    int sg = g_segq[p];
    float v[8];
#pragma unroll
    for (int r = 0; r < 8; r++) {
        int c = lane + 32 * r;
        v[r] = feat[(size_t)p * 256 + c] + g_mhca[(size_t)sg * 256 + c];
    }
#pragma unroll
    for (int j = 0; j < NOUT; j++) {
        float s = 0.f;
#pragma unroll
        for (int r = 0; r < 8; r++) s = fmaf(v[r], Ws[(lane + 32 * r) * NOUT + j], s);
#pragma unroll
        for (int o = 16; o; o >>= 1) s += __shfl_xor_sync(0xFFFFFFFFu, s, o);
        if (lane == 0) out[(size_t)p * NOUT + j] = s + bseg[j];
    }
}

// ---------------- host launch ----------------
static void* sym_addr(const void* symbol) {
    void* p = nullptr;
    cudaGetSymbolAddress(&p, symbol);
    return p;
}

extern "C" void kernel_launch(void* const* d_in, const int* in_sizes, int n_in,
                              void* d_out, int out_size) {
    const float* feat  = (const float*)d_in[0];
    const float* Wpool = (const float*)d_in[1];
    const float* bpool = (const float*)d_in[2];
    const float* Wemb  = (const float*)d_in[3];
    const float* bemb  = (const float*)d_in[4];
    const float* Wq    = (const float*)d_in[5];
    const float* bq    = (const float*)d_in[6];
    const float* Wk    = (const float*)d_in[7];
    const float* bk    = (const float*)d_in[8];
    const float* Wv    = (const float*)d_in[9];
    const float* bv    = (const float*)d_in[10];
    const float* Wo    = (const float*)d_in[11];
    const float* bo    = (const float*)d_in[12];
    const float* lng   = (const float*)d_in[13];
    const float* lnb   = (const float*)d_in[14];
    const float* Wseg  = (const float*)d_in[15];
    const float* bseg  = (const float*)d_in[16];
    const int*   ind   = (const int*)d_in[17];
    float* out = (float*)d_out;

    unsigned* p_pool_key = (unsigned*)sym_addr(g_pool_key);
    unsigned* p_emb_key  = (unsigned*)sym_addr(g_emb_key);
    int*      p_segq     = (int*)sym_addr(g_segq);
    int*      p_segk     = (int*)sym_addr(g_segk);
    int*      p_mask_q   = (int*)sym_addr(g_mask_q);
    int*      p_mask_k   = (int*)sym_addr(g_mask_k);
    int*      p_arg      = (int*)sym_addr(g_arg);
    float*    p_ef       = (float*)sym_addr(g_ef);
    float*    p_qin      = (float*)sym_addr(g_qin);
    float*    p_o2       = (float*)sym_addr(g_o2);
    float*    p_mhca     = (float*)sym_addr(g_mhca);
    __nv_bfloat16* p_featH = (__nv_bfloat16*)sym_addr(g_featH);
    __nv_bfloat16* p_featL = (__nv_bfloat16*)sym_addr(g_featL);
    __nv_bfloat16* p_wH    = (__nv_bfloat16*)sym_addr(g_wH);
    __nv_bfloat16* p_wL    = (__nv_bfloat16*)sym_addr(g_wL);
    __nv_bfloat16* p_qinH  = (__nv_bfloat16*)sym_addr(g_qinH);
    __nv_bfloat16* p_qinL  = (__nv_bfloat16*)sym_addr(g_qinL);
    __nv_bfloat16* p_kvH   = (__nv_bfloat16*)sym_addr(g_kvH);
    __nv_bfloat16* p_kvL   = (__nv_bfloat16*)sym_addr(g_kvL);
    __nv_bfloat16* p_qpH   = (__nv_bfloat16*)sym_addr(g_qpH);
    __nv_bfloat16* p_qpL   = (__nv_bfloat16*)sym_addr(g_qpL);
    __nv_bfloat16* p_oaH   = (__nv_bfloat16*)sym_addr(g_oaH);
    __nv_bfloat16* p_oaL   = (__nv_bfloat16*)sym_addr(g_oaL);
    __nv_bfloat16* p_k16h  = (__nv_bfloat16*)sym_addr(g_k16h);
    __nv_bfloat16* p_k16l  = (__nv_bfloat16*)sym_addr(g_k16l);
    __nv_bfloat16* p_v16h  = (__nv_bfloat16*)sym_addr(g_v16h);
    __nv_bfloat16* p_v16l  = (__nv_bfloat16*)sym_addr(g_v16l);

    cudaFuncSetAttribute(bf_gemm<10>, cudaFuncAttributeMaxDynamicSharedMemorySize, GEMM_SMEM);
    cudaFuncSetAttribute(bf_gemm<0>,  cudaFuncAttributeMaxDynamicSharedMemorySize, GEMM_SMEM);
    cudaFuncSetAttribute(bf_gemm<3>,  cudaFuncAttributeMaxDynamicSharedMemorySize, GEMM_SMEM);
    cudaFuncSetAttribute(bf_gemm<4>,  cudaFuncAttributeMaxDynamicSharedMemorySize, GEMM_SMEM);
    cudaFuncSetAttribute(bf_gemm<5>,  cudaFuncAttributeMaxDynamicSharedMemorySize, GEMM_SMEM);

    const float qscale = 0.17677669529663687f;

    // 1. init scratch (memsets) + prep + splits + PE table
    cudaMemsetAsync(p_pool_key, 0, (size_t)SQ * DIM * 4);
    cudaMemsetAsync(p_emb_key, 0, (size_t)SK * DIM * 4);
    cudaMemsetAsync(p_arg, 0xFF, (size_t)SK * DIM * 4);
    cudaMemsetAsync(p_mask_q, 0, SQ * 4);
    cudaMemsetAsync(p_mask_k, 0, SK * 4);
    prep_k<<<(NP + 255) / 256, 256>>>(ind);
    split_feat_k<<<(NP * DIM / 4 + 255) / 256, 256>>>(feat);
    split_w_k<<<(6 * 16384 + 255) / 256, 256>>>(Wpool, Wemb, Wq, Wk, Wv, Wo);
    pe_init_k<<<1, 64>>>();
    // 2. fused pool+emb GEMM (x: matrix(2) x col-half(2))
    bf_gemm<10><<<dim3(4, (NP + 127) / 128), 256, GEMM_SMEM>>>(
        p_featH, p_featL,
        p_wH + 0 * 65536, p_wL + 0 * 65536, bpool,
        p_wH + 1 * 65536, p_wL + 1 * 65536, bemb,
        p_ef, p_pool_key, p_segq, p_emb_key, p_segk,
        nullptr, nullptr, 0.f, NP);
    // 3. argmax + coords
    argmax_k<<<(NP * DIM) / 256, 256>>>();
    embc_k<<<SK, 256>>>(ind);
    // 4. PE grids
    buildq_k<<<SQ, 256>>>();
    buildkv_k<<<SK, 256>>>();
    // 5. projections
    bf_gemm<3><<<dim3(2, (SQ + 127) / 128), 256, GEMM_SMEM>>>(
        p_qinH, p_qinL, p_wH + 2 * 65536, p_wL + 2 * 65536, bq,
        nullptr, nullptr, nullptr, nullptr, nullptr, nullptr, nullptr, nullptr,
        p_qpH, p_qpL, qscale, SQ);
    bf_gemm<4><<<dim3(2, SK / 128), 256, GEMM_SMEM>>>(
        p_kvH, p_kvL, p_wH + 3 * 65536, p_wL + 3 * 65536, bk,
        nullptr, nullptr, nullptr, nullptr, nullptr, nullptr, nullptr, nullptr,
        p_k16h, p_k16l, 0.f, SK);
    bf_gemm<5><<<dim3(2, SK / 128), 256, GEMM_SMEM>>>(
        p_kvH, p_kvL, p_wH + 4 * 65536, p_wL + 4 * 65536, bv,
        nullptr, nullptr, nullptr, nullptr, nullptr, nullptr, nullptr, nullptr,
        p_v16h, p_v16l, 0.f, SK);
    // 6. fused flash attention
    fattn_k<<<dim3((GQ + 127) / 128, BATCH * NH), 256>>>(p_mask_k);
    // 7. output projection + residual + LN
    bf_gemm<0><<<dim3(2, (SQ + 127) / 128), 256, GEMM_SMEM>>>(
        p_oaH, p_oaL, p_wH + 5 * 65536, p_wL + 5 * 65536, bo,
        nullptr, nullptr, nullptr, p_o2, nullptr, nullptr, nullptr, nullptr,
        nullptr, nullptr, 0.f, SQ);
    ln_k<<<SQ, 256>>>(p_qin, p_o2, lng, lnb, p_mhca);
    // 8. gather + seg head
    head_k<<<NP / 8, 256>>>(feat, Wseg, bseg, out);
}

// round 8
// speedup vs baseline: 2.4639x; 1.1470x over previous
#include <cuda_runtime.h>
#include <cuda_bf16.h>
#include <math.h>
#include <stdint.h>

// ---------------- problem constants ----------------
#define NP   120000
#define DIM  256
#define BATCH 2
#define NH   8
#define NOUT 20
#define ZD 60
#define YD 45
#define XD 4
#define GQ 10800
#define SQ 21600
#define ZE 12
#define YE 24
#define XE 2
#define GK 576
#define SK 1152
#define NF 42
#define PEC 252

// ---------------- scratch ----------------
__device__ unsigned g_pool_key[SQ * DIM];
__device__ unsigned long long g_emb_key[SK * DIM];   // packed (fenc(v)<<32)|idx
__device__ int      g_mask_q[SQ];
__device__ int      g_mask_k[SK];
__device__ int      g_segq[NP];
__device__ int      g_segk[NP];
__device__ float    g_embc[SK * 3];
__device__ float    g_qin[(size_t)SQ * DIM];
__device__ float    g_o2[(size_t)SQ * DIM];
__device__ float    g_mhca[(size_t)SQ * DIM];
__device__ float    g_invt[64];
__device__ __nv_bfloat16 g_featH[(size_t)NP * DIM];
__device__ __nv_bfloat16 g_featL[(size_t)NP * DIM];
__device__ __nv_bfloat16 g_wH[6 * 65536];
__device__ __nv_bfloat16 g_wL[6 * 65536];
__device__ __nv_bfloat16 g_qinH[(size_t)SQ * DIM];
__device__ __nv_bfloat16 g_qinL[(size_t)SQ * DIM];
__device__ __nv_bfloat16 g_kvH[SK * DIM];
__device__ __nv_bfloat16 g_kvL[SK * DIM];
__device__ __nv_bfloat16 g_qpH[(size_t)SQ * DIM];
__device__ __nv_bfloat16 g_qpL[(size_t)SQ * DIM];
__device__ __nv_bfloat16 g_oaH[(size_t)SQ * DIM];
__device__ __nv_bfloat16 g_oaL[(size_t)SQ * DIM];
__device__ __nv_bfloat16 g_k16h[16 * 32 * 576];
__device__ __nv_bfloat16 g_k16l[16 * 32 * 576];
__device__ __nv_bfloat16 g_v16h[16 * 576 * 32];
__device__ __nv_bfloat16 g_v16l[16 * 576 * 32];

__device__ __forceinline__ unsigned fenc(float f) {
    unsigned u = __float_as_uint(f);
    return (u & 0x80000000u) ? ~u : (u | 0x80000000u);
}
__device__ __forceinline__ float fdec(unsigned k) {
    return __uint_as_float((k & 0x80000000u) ? (k ^ 0x80000000u) : ~k);
}

// ================= warp MMA helpers =================
__device__ __forceinline__ uint32_t sptr(const void* p) {
    return (uint32_t)__cvta_generic_to_shared(p);
}

#define LDSM_X4(r, addr) \
    asm volatile("ldmatrix.sync.aligned.m8n8.x4.shared.b16 {%0,%1,%2,%3}, [%4];" \
        : "=r"((r)[0]), "=r"((r)[1]), "=r"((r)[2]), "=r"((r)[3]) : "r"(addr))

#define LDSM_X4_T(r, addr) \
    asm volatile("ldmatrix.sync.aligned.m8n8.x4.trans.shared.b16 {%0,%1,%2,%3}, [%4];" \
        : "=r"((r)[0]), "=r"((r)[1]), "=r"((r)[2]), "=r"((r)[3]) : "r"(addr))

__device__ __forceinline__ void mma16816(float* c, const uint32_t* a, uint32_t b0, uint32_t b1) {
    asm volatile(
        "mma.sync.aligned.m16n8k16.row.col.f32.bf16.bf16.f32 "
        "{%0,%1,%2,%3}, {%4,%5,%6,%7}, {%8,%9}, {%0,%1,%2,%3};"
        : "+f"(c[0]), "+f"(c[1]), "+f"(c[2]), "+f"(c[3])
        : "r"(a[0]), "r"(a[1]), "r"(a[2]), "r"(a[3]), "r"(b0), "r"(b1));
}

#define CP16(dst, src) \
    asm volatile("cp.async.cg.shared.global [%0], [%1], 16;\n" :: "r"(dst), "l"(src))
#define CP_COMMIT asm volatile("cp.async.commit_group;\n" ::: "memory")
#define CP_WAIT1 asm volatile("cp.async.wait_group 1;\n" ::: "memory")
#define CP_WAIT0 asm volatile("cp.async.wait_group 0;\n" ::: "memory")

__device__ __forceinline__ void split_bf16(float v, __nv_bfloat16& h, __nv_bfloat16& l) {
    h = __float2bfloat16(v);
    l = __float2bfloat16(v - __bfloat162float(h));
}

__device__ __forceinline__ void split2pack(float a, float b, uint32_t& hi, uint32_t& lo) {
    __nv_bfloat16 ha = __float2bfloat16(a), hb = __float2bfloat16(b);
    __nv_bfloat16 la = __float2bfloat16(a - __bfloat162float(ha));
    __nv_bfloat16 lb = __float2bfloat16(b - __bfloat162float(hb));
    __nv_bfloat162 th(ha, hb), tl(la, lb);
    hi = *(uint32_t*)&th;
    lo = *(uint32_t*)&tl;
}

// ---------------- split kernels ----------------
__global__ void split_feat_k(const float* __restrict__ src) {
    size_t i = (size_t)blockIdx.x * 256 + threadIdx.x;
    if (i * 4 >= (size_t)NP * DIM) return;
    float4 v = ((const float4*)src)[i];
    __nv_bfloat16 hx, lx, hy, ly, hz, lz, hw, lw;
    split_bf16(v.x, hx, lx); split_bf16(v.y, hy, ly);
    split_bf16(v.z, hz, lz); split_bf16(v.w, hw, lw);
    ((__nv_bfloat162*)g_featH)[i * 2]     = __nv_bfloat162(hx, hy);
    ((__nv_bfloat162*)g_featH)[i * 2 + 1] = __nv_bfloat162(hz, hw);
    ((__nv_bfloat162*)g_featL)[i * 2]     = __nv_bfloat162(lx, ly);
    ((__nv_bfloat162*)g_featL)[i * 2 + 1] = __nv_bfloat162(lz, lw);
}

__global__ void split_w_k(const float* __restrict__ w0, const float* __restrict__ w1,
                          const float* __restrict__ w2, const float* __restrict__ w3,
                          const float* __restrict__ w4, const float* __restrict__ w5) {
    int i = blockIdx.x * 256 + threadIdx.x;
    if (i >= 6 * 16384) return;
    int which = i >> 14;
    int off = i & 16383;
    const float* src = which == 0 ? w0 : which == 1 ? w1 : which == 2 ? w2
                     : which == 3 ? w3 : which == 4 ? w4 : w5;
    float4 v = ((const float4*)src)[off];
    __nv_bfloat16 hx, lx, hy, ly, hz, lz, hw, lw;
    split_bf16(v.x, hx, lx); split_bf16(v.y, hy, ly);
    split_bf16(v.z, hz, lz); split_bf16(v.w, hw, lw);
    ((__nv_bfloat162*)g_wH)[i * 2]     = __nv_bfloat162(hx, hy);
    ((__nv_bfloat162*)g_wH)[i * 2 + 1] = __nv_bfloat162(hz, hw);
    ((__nv_bfloat162*)g_wL)[i * 2]     = __nv_bfloat162(lx, ly);
    ((__nv_bfloat162*)g_wL)[i * 2 + 1] = __nv_bfloat162(lz, lw);
}

__global__ void pe_init_k() {
    int j = threadIdx.x;
    if (j < NF) g_invt[j] = 1.0f / powf(10000.0f, (float)j / (float)NF);
}

// ================= pipelined bf16x3 MMA GEMM =====================
// CTA tile 128m x 128n; 8 warps 2x4, warp tile 64x32; 2-stage cp.async; K chunk 32.
// MODE 10: fused pool/emb: x>>1 selects matrix; pool -> 32-bit atomicMax keyP,
//          emb -> 64-bit packed (fenc<<32|idx) atomicMax keyE (value+argmax fused).
#define AP 40
#define BP 136
#define SA_BYTES (2 * 2 * 128 * AP * 2)
#define SB_BYTES (2 * 2 * 32 * BP * 2)
#define GEMM_SMEM (SA_BYTES + SB_BYTES)

__device__ __forceinline__ __nv_bfloat16* pA(__nv_bfloat16* b, int st, int mat, int r) {
    return b + ((st * 2 + mat) * 128 + r) * AP;
}
__device__ __forceinline__ __nv_bfloat16* pB(__nv_bfloat16* b, int st, int mat, int r) {
    return b + ((st * 2 + mat) * 32 + r) * BP;
}

template <int MODE>
__global__ __launch_bounds__(256, 2) void bf_gemm(
    const __nv_bfloat16* __restrict__ Ah, const __nv_bfloat16* __restrict__ Al,
    const __nv_bfloat16* __restrict__ WhA, const __nv_bfloat16* __restrict__ WlA,
    const float* __restrict__ biasA,
    const __nv_bfloat16* __restrict__ WhB, const __nv_bfloat16* __restrict__ WlB,
    const float* __restrict__ biasB,
    float* __restrict__ Cout,
    unsigned* __restrict__ keyP, const int* __restrict__ segP,
    unsigned long long* __restrict__ keyE, const int* __restrict__ segE,
    __nv_bfloat16* __restrict__ outH, __nv_bfloat16* __restrict__ outL,
    float scale, int M)
{
    extern __shared__ char dsm[];
    __nv_bfloat16* sA = (__nv_bfloat16*)dsm;
    __nv_bfloat16* sB = (__nv_bfloat16*)(dsm + SA_BYTES);

    int t = threadIdx.x, wid = t >> 5, lane = t & 31;
    int wm = wid >> 2, wn = wid & 3;
    int m0 = blockIdx.y * 128;

    bool isPool = false;
    const __nv_bfloat16 *Whp = WhA, *Wlp = WlA;
    const float* bp = biasA;
    int c0;
    if (MODE == 10) {
        isPool = ((blockIdx.x >> 1) == 0);
        if (!isPool) { Whp = WhB; Wlp = WlB; bp = biasB; }
        c0 = (blockIdx.x & 1) * 128;
    } else {
        c0 = blockIdx.x * 128;
    }

    float acc[4][4][4] = {};

    auto copyA = [&](int st, int ch) {
        int k0 = ch * 32;
#pragma unroll
        for (int i = 0; i < 2; i++) {
            int op = t * 2 + i;
            int r = op >> 2, seg = op & 3;
            int rowc = m0 + r;
            if (rowc >= M) rowc = M - 1;
            size_t src = (size_t)rowc * 256 + k0 + seg * 8;
            CP16(sptr(pA(sA, st, 0, r) + seg * 8), Ah + src);
            CP16(sptr(pA(sA, st, 1, r) + seg * 8), Al + src);
        }
    };
    auto copyB = [&](int st, int ch) {
        int k0 = ch * 32;
        int r = t >> 3;
#pragma unroll
        for (int q = 0; q < 2; q++) {
            int seg = (t & 7) + q * 8;
            size_t src = (size_t)(k0 + r) * 256 + c0 + seg * 8;
            CP16(sptr(pB(sB, st, 0, r) + seg * 8), Whp + src);
            CP16(sptr(pB(sB, st, 1, r) + seg * 8), Wlp + src);
        }
    };

    copyA(0, 0);
    copyB(0, 0);
    CP_COMMIT;

    for (int ch = 0; ch < 8; ch++) {
        if (ch < 7) {
            copyA((ch + 1) & 1, ch + 1);
            copyB((ch + 1) & 1, ch + 1);
            CP_COMMIT;
            CP_WAIT1;
        } else {
            CP_WAIT0;
        }
        __syncthreads();
        int st = ch & 1;
#pragma unroll
        for (int ks = 0; ks < 2; ks++) {
            int arow = wm * 64 + (lane & 15);
            int akc = ks * 16 + ((lane & 16) ? 8 : 0);
            int bkr = ks * 16 + (lane & 15);
            int bnc = wn * 32 + ((lane & 16) ? 8 : 0);

            uint32_t af[4][4], bh[8], bl[8];
#pragma unroll
            for (int mt = 0; mt < 4; mt++)
                LDSM_X4(af[mt], sptr(pA(sA, st, 0, arow + mt * 16) + akc));
            LDSM_X4_T(bh,     sptr(pB(sB, st, 0, bkr) + bnc));
            LDSM_X4_T(bh + 4, sptr(pB(sB, st, 0, bkr) + bnc + 16));
            LDSM_X4_T(bl,     sptr(pB(sB, st, 1, bkr) + bnc));
            LDSM_X4_T(bl + 4, sptr(pB(sB, st, 1, bkr) + bnc + 16));

#pragma unroll
            for (int mt = 0; mt < 4; mt++) {
#pragma unroll
                for (int nt = 0; nt < 4; nt++) {
                    mma16816(acc[mt][nt], af[mt], bh[nt * 2], bh[nt * 2 + 1]);
                    mma16816(acc[mt][nt], af[mt], bl[nt * 2], bl[nt * 2 + 1]);
                }
            }
#pragma unroll
            for (int mt = 0; mt < 4; mt++)
                LDSM_X4(af[mt], sptr(pA(sA, st, 1, arow + mt * 16) + akc));
#pragma unroll
            for (int mt = 0; mt < 4; mt++) {
#pragma unroll
                for (int nt = 0; nt < 4; nt++)
                    mma16816(acc[mt][nt], af[mt], bh[nt * 2], bh[nt * 2 + 1]);
            }
        }
        __syncthreads();
    }

    // ---- epilogue ----
    int g = lane >> 2, tid4 = lane & 3;
#pragma unroll
    for (int mt = 0; mt < 4; mt++) {
#pragma unroll
        for (int nt = 0; nt < 4; nt++) {
            int coln = c0 + wn * 32 + nt * 8 + tid4 * 2;
            float b0 = bp[coln], b1 = bp[coln + 1];
#pragma unroll
            for (int half = 0; half < 2; half++) {
                int m = m0 + wm * 64 + mt * 16 + g + half * 8;
                if (m >= M) continue;
                float v0 = acc[mt][nt][half * 2 + 0] + b0;
                float v1 = acc[mt][nt][half * 2 + 1] + b1;
                if (MODE == 0) {
                    Cout[(size_t)m * 256 + coln]     = v0;
                    Cout[(size_t)m * 256 + coln + 1] = v1;
                } else if (MODE == 10) {
                    if (isPool) {
                        int sg = segP[m];
                        atomicMax(&keyP[sg * 256 + coln],     fenc(v0));
                        atomicMax(&keyP[sg * 256 + coln + 1], fenc(v1));
                    } else {
                        int sg = segE[m];
                        unsigned long long p0 = ((unsigned long long)fenc(v0) << 32) | (unsigned)m;
                        unsigned long long p1 = ((unsigned long long)fenc(v1) << 32) | (unsigned)m;
                        atomicMax(&keyE[sg * 256 + coln],     p0);
                        atomicMax(&keyE[sg * 256 + coln + 1], p1);
                    }
                } else if (MODE == 3) {
                    uint32_t hi, lo;
                    split2pack(v0 * scale, v1 * scale, hi, lo);
                    *(uint32_t*)&outH[(size_t)m * 256 + coln] = hi;
                    *(uint32_t*)&outL[(size_t)m * 256 + coln] = lo;
                } else if (MODE == 4) {
                    int b_ = m / 576, key = m - b_ * 576;
                    int hh = coln >> 5, d = coln & 31;
                    __nv_bfloat16 H, L;
                    split_bf16(v0, H, L);
                    size_t dst0 = (size_t)((b_ * 8 + hh) * 32 + d) * 576 + key;
                    outH[dst0] = H; outL[dst0] = L;
                    split_bf16(v1, H, L);
                    outH[dst0 + 576] = H; outL[dst0 + 576] = L;
                } else if (MODE == 5) {
                    int b_ = m / 576, key = m - b_ * 576;
                    int hh = coln >> 5, d = coln & 31;
                    __nv_bfloat16 H, L;
                    size_t dst0 = ((size_t)(b_ * 8 + hh) * 576 + key) * 32 + d;
                    split_bf16(v0, H, L);
                    outH[dst0] = H; outL[dst0] = L;
                    split_bf16(v1, H, L);
                    outH[dst0 + 1] = H; outL[dst0 + 1] = L;
                }
            }
        }
    }
}

// ---------------- per-point segment ids + occupancy masks ----------------
__global__ void prep_k(const int* __restrict__ ind) {
    int i = blockIdx.x * 256 + threadIdx.x;
    if (i >= NP) return;
    int b = ind[i * 4 + 0];
    int z = ind[i * 4 + 1];
    int y = ind[i * 4 + 2];
    int x = ind[i * 4 + 3];
    int sq = ((b * ZD + z / 8) * YD + y / 8) * XD + x / 8;
    int sk = ((b * ZE + z / 40) * YE + y / 15) * XE + x / 16;
    g_segq[i] = sq;
    g_segk[i] = sk;
    g_mask_q[sq] = 1;
    g_mask_k[sk] = 1;
}

// ---------------- emb coords (winner index from packed key) ----------------
__global__ void embc_k(const int* __restrict__ ind) {
    __shared__ float rz[256], ry[256], rx[256];
    int s = blockIdx.x;
    int t = threadIdx.x;
    int i = (int)(g_emb_key[s * 256 + t] & 0xFFFFFFFFull);   // empty seg -> 0 (== clip(-1,0))
    int z = ind[i * 4 + 1], y = ind[i * 4 + 2], x = ind[i * 4 + 3];
    rz[t] = (float)(z / 40);
    ry[t] = (float)(y / 15);
    rx[t] = (float)(x / 16);
    __syncthreads();
    for (int o = 128; o > 0; o >>= 1) {
        if (t < o) { rz[t] += rz[t + o]; ry[t] += ry[t + o]; rx[t] += rx[t + o]; }
        __syncthreads();
    }
    if (t == 0) {
        g_embc[s * 3 + 0] = rz[0] * (1.f / 256.f) * 40.f;
        g_embc[s * 3 + 1] = ry[0] * (1.f / 256.f) * 15.f;
        g_embc[s * 3 + 2] = rx[0] * (1.f / 256.f) * 16.f;
    }
}

// ---------------- sine PE (table + fast intrinsics) ----------------
__device__ __forceinline__ float pe_val(float cz, float cy, float cx, int c) {
    if (c >= PEC) return 0.f;
    int axis = c / (2 * NF);
    int r = c - axis * (2 * NF);
    int j = r < NF ? r : r - NF;
    float coord = (axis == 0) ? cz : (axis == 1) ? cy : cx;
    float spd = (axis == 0) ? 480.f : (axis == 1) ? 360.f : 32.f;
    float ang = coord / spd * 6.283185307179586f * g_invt[j];
    return (r < NF) ? __sinf(ang) : __cosf(ang);
}

__global__ void buildq_k() {
    int s = blockIdx.x;
    int c = threadIdx.x;
    int rem = s % GQ;
    float cz = (float)((rem / (YD * XD)) * 8);
    float cy = (float)(((rem / XD) % YD) * 8);
    float cx = (float)((rem % XD) * 8);
    float base = g_mask_q[s] ? fdec(g_pool_key[(size_t)s * 256 + c]) : 0.f;
    float val = base + pe_val(cz, cy, cx, c);
    size_t idx = (size_t)s * 256 + c;
    g_qin[idx] = val;
    __nv_bfloat16 h, l;
    split_bf16(val, h, l);
    g_qinH[idx] = h;
    g_qinL[idx] = l;
}

__global__ void buildkv_k() {
    int s = blockIdx.x;
    int c = threadIdx.x;
    float cz = g_embc[s * 3 + 0];
    float cy = g_embc[s * 3 + 1];
    float cx = g_embc[s * 3 + 2];
    float base = g_mask_k[s] ? fdec((unsigned)(g_emb_key[s * 256 + c] >> 32)) : 0.f;
    float val = base + pe_val(cz, cy, cx, c);
    __nv_bfloat16 h, l;
    split_bf16(val, h, l);
    g_kvH[s * 256 + c] = h;
    g_kvL[s * 256 + c] = l;
}

// ---------------- fused flash attention, 256 threads / 128 q rows ----------------
#define QPAD 40
#define KPAD 72
__global__ __launch_bounds__(256) void fattn_k(const int* __restrict__ maskk) {
    __shared__ __align__(16) __nv_bfloat16 sQ[2][128][QPAD];
    __shared__ __align__(16) __nv_bfloat16 sK[2][32][KPAD];
    __shared__ __align__(16) __nv_bfloat16 sV[2][64][QPAD];
    __shared__ int smask[GK];

    int t = threadIdx.x, wid = t >> 5, lane = t & 31;
    int bh = blockIdx.y, b = bh >> 3, h = bh & 7;
    int q0 = blockIdx.x * 128;

    {
#pragma unroll
        for (int i = 0; i < 2; i++) {
            int op = t * 2 + i;
            int r = op >> 2, seg = op & 3;
            uint4 vh = make_uint4(0, 0, 0, 0), vl = vh;
            if (q0 + r < GQ) {
                size_t s = (size_t)(b * GQ + q0 + r) * 256 + h * 32 + seg * 8;
                vh = *(const uint4*)&g_qpH[s];
                vl = *(const uint4*)&g_qpL[s];
            }
            *(uint4*)&sQ[0][r][seg * 8] = vh;
            *(uint4*)&sQ[1][r][seg * 8] = vl;
        }
    }
    for (int i = t; i < GK; i += 256) smask[i] = maskk[b * GK + i];
    __syncthreads();

    uint32_t qh[2][4], ql[2][4];
    {
        int arow = wid * 16 + (lane & 15);
#pragma unroll
        for (int s = 0; s < 2; s++) {
            int akc = s * 16 + ((lane & 16) ? 8 : 0);
            LDSM_X4(qh[s], sptr(&sQ[0][arow][akc]));
            LDSM_X4(ql[s], sptr(&sQ[1][arow][akc]));
        }
    }

    float m0r = -INFINITY, m1r = -INFINITY, l0 = 0.f, l1 = 0.f;
    float oacc[4][4] = {};
    int g = lane >> 2, tid4 = lane & 3;
    int bkr = lane & 15;
    int bsel = (lane & 16) ? 8 : 0;

    for (int c = 0; c < 9; c++) {
        {
            int d = t >> 3, ks = (t & 7) * 8;
            size_t src = (size_t)(bh * 32 + d) * 576 + c * 64 + ks;
            *(uint4*)&sK[0][d][ks] = *(const uint4*)&g_k16h[src];
            *(uint4*)&sK[1][d][ks] = *(const uint4*)&g_k16l[src];
        }
        {
            int key = t >> 2, ds = (t & 3) * 8;
            size_t src = (size_t)(bh * 576 + c * 64 + key) * 32 + ds;
            *(uint4*)&sV[0][key][ds] = *(const uint4*)&g_v16h[src];
            *(uint4*)&sV[1][key][ds] = *(const uint4*)&g_v16l[src];
        }
        __syncthreads();

        float acc[8][4] = {};
#pragma unroll
        for (int s = 0; s < 2; s++) {
#pragma unroll
            for (int j = 0; j < 4; j++) {
                uint32_t kh_[4], kl_[4];
                LDSM_X4_T(kh_, sptr(&sK[0][s * 16 + bkr][j * 16 + bsel]));
                LDSM_X4_T(kl_, sptr(&sK[1][s * 16 + bkr][j * 16 + bsel]));
                mma16816(acc[2 * j],     qh[s], kh_[0], kh_[1]);
                mma16816(acc[2 * j],     qh[s], kl_[0], kl_[1]);
                mma16816(acc[2 * j],     ql[s], kh_[0], kh_[1]);
                mma16816(acc[2 * j + 1], qh[s], kh_[2], kh_[3]);
                mma16816(acc[2 * j + 1], qh[s], kl_[2], kl_[3]);
                mma16816(acc[2 * j + 1], ql[s], kh_[2], kh_[3]);
            }
        }
#pragma unroll
        for (int j = 0; j < 8; j++) {
            int key = c * 64 + j * 8 + tid4 * 2;
            if (!smask[key])     { acc[j][0] = -1e9f; acc[j][2] = -1e9f; }
            if (!smask[key + 1]) { acc[j][1] = -1e9f; acc[j][3] = -1e9f; }
        }
        float mx0 = -INFINITY, mx1 = -INFINITY;
#pragma unroll
        for (int j = 0; j < 8; j++) {
            mx0 = fmaxf(mx0, fmaxf(acc[j][0], acc[j][1]));
            mx1 = fmaxf(mx1, fmaxf(acc[j][2], acc[j][3]));
        }
        mx0 = fmaxf(mx0, __shfl_xor_sync(0xFFFFFFFFu, mx0, 1));
        mx0 = fmaxf(mx0, __shfl_xor_sync(0xFFFFFFFFu, mx0, 2));
        mx1 = fmaxf(mx1, __shfl_xor_sync(0xFFFFFFFFu, mx1, 1));
        mx1 = fmaxf(mx1, __shfl_xor_sync(0xFFFFFFFFu, mx1, 2));
        float mn0 = fmaxf(m0r, mx0), mn1 = fmaxf(m1r, mx1);
        float rs0 = __expf(m0r - mn0), rs1 = __expf(m1r - mn1);
        float sum0 = 0.f, sum1 = 0.f;
#pragma unroll
        for (int j = 0; j < 8; j++) {
            acc[j][0] = __expf(acc[j][0] - mn0);
            acc[j][1] = __expf(acc[j][1] - mn0);
            acc[j][2] = __expf(acc[j][2] - mn1);
            acc[j][3] = __expf(acc[j][3] - mn1);
            sum0 += acc[j][0] + acc[j][1];
            sum1 += acc[j][2] + acc[j][3];
        }
        sum0 += __shfl_xor_sync(0xFFFFFFFFu, sum0, 1);
        sum0 += __shfl_xor_sync(0xFFFFFFFFu, sum0, 2);
        sum1 += __shfl_xor_sync(0xFFFFFFFFu, sum1, 1);
        sum1 += __shfl_xor_sync(0xFFFFFFFFu, sum1, 2);
        l0 = l0 * rs0 + sum0;
        l1 = l1 * rs1 + sum1;
#pragma unroll
        for (int dt = 0; dt < 4; dt++) {
            oacc[dt][0] *= rs0; oacc[dt][1] *= rs0;
            oacc[dt][2] *= rs1; oacc[dt][3] *= rs1;
        }
        m0r = mn0; m1r = mn1;

#pragma unroll
        for (int kt = 0; kt < 4; kt++) {
            uint32_t pha[4], pla[4];
            split2pack(acc[2 * kt][0],     acc[2 * kt][1],     pha[0], pla[0]);
            split2pack(acc[2 * kt][2],     acc[2 * kt][3],     pha[1], pla[1]);
            split2pack(acc[2 * kt + 1][0], acc[2 * kt + 1][1], pha[2], pla[2]);
            split2pack(acc[2 * kt + 1][2], acc[2 * kt + 1][3], pha[3], pla[3]);
#pragma unroll
            for (int dh2 = 0; dh2 < 2; dh2++) {
                uint32_t vh_[4], vl_[4];
                LDSM_X4_T(vh_, sptr(&sV[0][kt * 16 + bkr][dh2 * 16 + bsel]));
                LDSM_X4_T(vl_, sptr(&sV[1][kt * 16 + bkr][dh2 * 16 + bsel]));
                mma16816(oacc[dh2 * 2],     pha, vh_[0], vh_[1]);
                mma16816(oacc[dh2 * 2],     pha, vl_[0], vl_[1]);
                mma16816(oacc[dh2 * 2],     pla, vh_[0], vh_[1]);
                mma16816(oacc[dh2 * 2 + 1], pha, vh_[2], vh_[3]);
                mma16816(oacc[dh2 * 2 + 1], pha, vl_[2], vl_[3]);
                mma16816(oacc[dh2 * 2 + 1], pla, vh_[2], vh_[3]);
            }
        }
        __syncthreads();
    }

    float inv0 = 1.f / l0, inv1 = 1.f / l1;
    int qa = q0 + wid * 16 + g;
    int qb = qa + 8;
#pragma unroll
    for (int dt = 0; dt < 4; dt++) {
        int dim = h * 32 + dt * 8 + tid4 * 2;
        if (qa < GQ) {
            uint32_t hi, lo;
            split2pack(oacc[dt][0] * inv0, oacc[dt][1] * inv0, hi, lo);
            *(uint32_t*)&g_oaH[(size_t)(b * GQ + qa) * 256 + dim] = hi;
            *(uint32_t*)&g_oaL[(size_t)(b * GQ + qa) * 256 + dim] = lo;
        }
        if (qb < GQ) {
            uint32_t hi, lo;
            split2pack(oacc[dt][2] * inv1, oacc[dt][3] * inv1, hi, lo);
            *(uint32_t*)&g_oaH[(size_t)(b * GQ + qb) * 256 + dim] = hi;
            *(uint32_t*)&g_oaL[(size_t)(b * GQ + qb) * 256 + dim] = lo;
        }
    }
}

// ---------------- residual + LayerNorm ----------------
__global__ void ln_k(const float* __restrict__ qin, const float* __restrict__ o2,
                     const float* __restrict__ g, const float* __restrict__ bb,
                     float* __restrict__ out) {
    __shared__ float red[256];
    __shared__ float mu_s, var_s;
    int r = blockIdx.x;
    int c = threadIdx.x;
    float h = qin[(size_t)r * 256 + c] + o2[(size_t)r * 256 + c];
    red[c] = h;
    __syncthreads();
    for (int o = 128; o > 0; o >>= 1) {
        if (c < o) red[c] += red[c + o];
        __syncthreads();
    }
    if (c == 0) mu_s = red[0] * (1.f / 256.f);
    __syncthreads();
    float d = h - mu_s;
    red[c] = d * d;
    __syncthreads();
    for (int o = 128; o > 0; o >>= 1) {
        if (c < o) red[c] += red[c + o];
        __syncthreads();
    }
    if (c == 0) var_s = red[0] * (1.f / 256.f);
    __syncthreads();
    out[(size_t)r * 256 + c] = d * rsqrtf(var_s + 1e-5f) * g[c] + bb[c];
}

// ---------------- final gather + seg head ----------------
__global__ void head_k(const float* __restrict__ feat, const float* __restrict__ Wseg,
                       const float* __restrict__ bseg, float* __restrict__ out) {
    __shared__ float Ws[256 * NOUT];
    int t = threadIdx.x;
    for (int i = t; i < 256 * NOUT; i += 256) Ws[i] = Wseg[i];
    __syncthreads();
    int p = blockIdx.x * 8 + (t >> 5);
    int lane = t & 31;
    int sg = g_segq[p];
    float v[8];
#pragma unroll
    for (int r = 0; r < 8; r++) {
        int c = lane + 32 * r;
        v[r] = feat[(size_t)p * 256 + c] + g_mhca[(size_t)sg * 256 + c];
    }
#pragma unroll
    for (int j = 0; j < NOUT; j++) {
        float s = 0.f;
#pragma unroll
        for (int r = 0; r < 8; r++) s = fmaf(v[r], Ws[(lane + 32 * r) * NOUT + j], s);
#pragma unroll
        for (int o = 16; o; o >>= 1) s += __shfl_xor_sync(0xFFFFFFFFu, s, o);
        if (lane == 0) out[(size_t)p * NOUT + j] = s + bseg[j];
    }
}

// ---------------- host launch ----------------
static void* sym_addr(const void* symbol) {
    void* p = nullptr;
    cudaGetSymbolAddress(&p, symbol);
    return p;
}

extern "C" void kernel_launch(void* const* d_in, const int* in_sizes, int n_in,
                              void* d_out, int out_size) {
    const float* feat  = (const float*)d_in[0];
    const float* Wpool = (const float*)d_in[1];
    const float* bpool = (const float*)d_in[2];
    const float* Wemb  = (const float*)d_in[3];
    const float* bemb  = (const float*)d_in[4];
    const float* Wq    = (const float*)d_in[5];
    const float* bq    = (const float*)d_in[6];
    const float* Wk    = (const float*)d_in[7];
    const float* bk    = (const float*)d_in[8];
    const float* Wv    = (const float*)d_in[9];
    const float* bv    = (const float*)d_in[10];
    const float* Wo    = (const float*)d_in[11];
    const float* bo    = (const float*)d_in[12];
    const float* lng   = (const float*)d_in[13];
    const float* lnb   = (const float*)d_in[14];
    const float* Wseg  = (const float*)d_in[15];
    const float* bseg  = (const float*)d_in[16];
    const int*   ind   = (const int*)d_in[17];
    float* out = (float*)d_out;

    unsigned* p_pool_key = (unsigned*)sym_addr(g_pool_key);
    unsigned long long* p_emb_key = (unsigned long long*)sym_addr(g_emb_key);
    int*      p_segq     = (int*)sym_addr(g_segq);
    int*      p_segk     = (int*)sym_addr(g_segk);
    int*      p_mask_q   = (int*)sym_addr(g_mask_q);
    int*      p_mask_k   = (int*)sym_addr(g_mask_k);
    float*    p_qin      = (float*)sym_addr(g_qin);
    float*    p_o2       = (float*)sym_addr(g_o2);
    float*    p_mhca     = (float*)sym_addr(g_mhca);
    __nv_bfloat16* p_featH = (__nv_bfloat16*)sym_addr(g_featH);
    __nv_bfloat16* p_featL = (__nv_bfloat16*)sym_addr(g_featL);
    __nv_bfloat16* p_wH    = (__nv_bfloat16*)sym_addr(g_wH);
    __nv_bfloat16* p_wL    = (__nv_bfloat16*)sym_addr(g_wL);
    __nv_bfloat16* p_qinH  = (__nv_bfloat16*)sym_addr(g_qinH);
    __nv_bfloat16* p_qinL  = (__nv_bfloat16*)sym_addr(g_qinL);
    __nv_bfloat16* p_kvH   = (__nv_bfloat16*)sym_addr(g_kvH);
    __nv_bfloat16* p_kvL   = (__nv_bfloat16*)sym_addr(g_kvL);
    __nv_bfloat16* p_qpH   = (__nv_bfloat16*)sym_addr(g_qpH);
    __nv_bfloat16* p_qpL   = (__nv_bfloat16*)sym_addr(g_qpL);
    __nv_bfloat16* p_oaH   = (__nv_bfloat16*)sym_addr(g_oaH);
    __nv_bfloat16* p_oaL   = (__nv_bfloat16*)sym_addr(g_oaL);
    __nv_bfloat16* p_k16h  = (__nv_bfloat16*)sym_addr(g_k16h);
    __nv_bfloat16* p_k16l  = (__nv_bfloat16*)sym_addr(g_k16l);
    __nv_bfloat16* p_v16h  = (__nv_bfloat16*)sym_addr(g_v16h);
    __nv_bfloat16* p_v16l  = (__nv_bfloat16*)sym_addr(g_v16l);

    cudaFuncSetAttribute(bf_gemm<10>, cudaFuncAttributeMaxDynamicSharedMemorySize, GEMM_SMEM);
    cudaFuncSetAttribute(bf_gemm<0>,  cudaFuncAttributeMaxDynamicSharedMemorySize, GEMM_SMEM);
    cudaFuncSetAttribute(bf_gemm<3>,  cudaFuncAttributeMaxDynamicSharedMemorySize, GEMM_SMEM);
    cudaFuncSetAttribute(bf_gemm<4>,  cudaFuncAttributeMaxDynamicSharedMemorySize, GEMM_SMEM);
    cudaFuncSetAttribute(bf_gemm<5>,  cudaFuncAttributeMaxDynamicSharedMemorySize, GEMM_SMEM);

    const float qscale = 0.17677669529663687f;

    // 1. init scratch (memsets) + prep + splits + PE table
    cudaMemsetAsync(p_pool_key, 0, (size_t)SQ * DIM * 4);
    cudaMemsetAsync(p_emb_key, 0, (size_t)SK * DIM * 8);
    cudaMemsetAsync(p_mask_q, 0, SQ * 4);
    cudaMemsetAsync(p_mask_k, 0, SK * 4);
    prep_k<<<(NP + 255) / 256, 256>>>(ind);
    split_feat_k<<<(NP * DIM / 4 + 255) / 256, 256>>>(feat);
    split_w_k<<<(6 * 16384 + 255) / 256, 256>>>(Wpool, Wemb, Wq, Wk, Wv, Wo);
    pe_init_k<<<1, 64>>>();
    // 2. fused pool+emb GEMM (value scatter + packed argmax in one pass)
    bf_gemm<10><<<dim3(4, (NP + 127) / 128), 256, GEMM_SMEM>>>(
        p_featH, p_featL,
        p_wH + 0 * 65536, p_wL + 0 * 65536, bpool,
        p_wH + 1 * 65536, p_wL + 1 * 65536, bemb,
        nullptr, p_pool_key, p_segq, p_emb_key, p_segk,
        nullptr, nullptr, 0.f, NP);
    // 3. winner coords
    embc_k<<<SK, 256>>>(ind);
    // 4. PE grids
    buildq_k<<<SQ, 256>>>();
    buildkv_k<<<SK, 256>>>();
    // 5. projections
    bf_gemm<3><<<dim3(2, (SQ + 127) / 128), 256, GEMM_SMEM>>>(
        p_qinH, p_qinL, p_wH + 2 * 65536, p_wL + 2 * 65536, bq,
        nullptr, nullptr, nullptr, nullptr, nullptr, nullptr, nullptr, nullptr,
        p_qpH, p_qpL, qscale, SQ);
    bf_gemm<4><<<dim3(2, SK / 128), 256, GEMM_SMEM>>>(
        p_kvH, p_kvL, p_wH + 3 * 65536, p_wL + 3 * 65536, bk,
        nullptr, nullptr, nullptr, nullptr, nullptr, nullptr, nullptr, nullptr,
        p_k16h, p_k16l, 0.f, SK);
    bf_gemm<5><<<dim3(2, SK / 128), 256, GEMM_SMEM>>>(
        p_kvH, p_kvL, p_wH + 4 * 65536, p_wL + 4 * 65536, bv,
        nullptr, nullptr, nullptr, nullptr, nullptr, nullptr, nullptr, nullptr,
        p_v16h, p_v16l, 0.f, SK);
    // 6. fused flash attention
    fattn_k<<<dim3((GQ + 127) / 128, BATCH * NH), 256>>>(p_mask_k);
    // 7. output projection + residual + LN
    bf_gemm<0><<<dim3(2, (SQ + 127) / 128), 256, GEMM_SMEM>>>(
        p_oaH, p_oaL, p_wH + 5 * 65536, p_wL + 5 * 65536, bo,
        nullptr, nullptr, nullptr, p_o2, nullptr, nullptr, nullptr, nullptr,
        nullptr, nullptr, 0.f, SQ);
    ln_k<<<SQ, 256>>>(p_qin, p_o2, lng, lnb, p_mhca);
    // 8. gather + seg head
    head_k<<<NP / 8, 256>>>(feat, Wseg, bseg, out);
}